// round 14
// baseline (speedup 1.0000x reference)
#include <cuda_runtime.h>
#include <math.h>

#define EPS 1e-8f
#define B_   32
#define CPD_ 32
#define F_   1024
#define D_   1024
#define S_   128
#define BF_  (B_*F_)        // 32768
#define W_   16             // chunk width
#define NC_  64             // number of chunks

typedef unsigned long long u64;

// ---------------- device scratch ----------------
__device__ float g_WD[CPD_*D_];        // W @ direct   [32][1024]
__device__ float g_WB[CPD_*S_];        // W @ input    [32][128]
__device__ float g_G[CPD_*CPD_];       // W W^T
__device__ float g_GD[CPD_*CPD_];      // WD WD^T
__device__ float g_GB[CPD_*CPD_];      // WB WB^T
__device__ float g_GO[S_*S_];          // Om Om^T
__device__ float g_WDwt[D_*CPD_];      // window-folded WD transpose [j][i]
__device__ float g_Omw[256*512];       // window-folded stacked Om [256][512]
__device__ float g_cd[(size_t)BF_*CPD_]; // fd-scaled control rows [r][32]
__device__ float g_cb[(size_t)BF_*CPD_]; // fb-scaled control rows [r][32]
__device__ float g_yb[(size_t)BF_*S_]; // b rows [f*32+b][128]
__device__ float g_nb2[BF_];           // ||b||^2 per frame
__device__ float g_Mp[17*S_*S_];       // M^0..M^16
__device__ float g_WBMp[W_*CPD_*S_];   // WB @ M^(15-i), i=0..15
__device__ float g_rc[NC_*B_*S_];      // chunk residuals
__device__ float g_S[NC_*B_*S_];       // chunk-start states
__device__ float g_x[(size_t)BF_*S_];  // speculative x_t = s_t M
__device__ float g_sp[(size_t)BF_*S_]; // s'_t rows
__device__ float g_nsp[BF_];           // ||s'_t||
__device__ float g_fc[BF_];            // c factor
__device__ int   g_bad;                // clamp-active flag

// ---------------- f32x2 helpers ----------------
__device__ __forceinline__ void fma2(u64 &acc, u64 a, u64 b) {
    asm("fma.rn.f32x2 %0, %1, %2, %0;" : "+l"(acc) : "l"(a), "l"(b));
}
__device__ __forceinline__ u64 pk2(float lo, float hi) {
    u64 r; asm("mov.b64 %0, {%1, %2};" : "=l"(r) : "f"(lo), "f"(hi)); return r;
}
__device__ __forceinline__ float2 upk2(u64 v) {
    float lo, hi; asm("mov.b64 {%0, %1}, %2;" : "=f"(lo), "=f"(hi) : "l"(v));
    return make_float2(lo, hi);
}
__device__ __forceinline__ float warp_sum(float v) {
#pragma unroll
    for (int m = 16; m > 0; m >>= 1) v += __shfl_xor_sync(0xffffffffu, v, m);
    return v;
}
__device__ __forceinline__ void warp_sum2(float &a, float &b) {
#pragma unroll
    for (int m = 16; m > 0; m >>= 1) {
        a += __shfl_xor_sync(0xffffffffu, a, m);
        b += __shfl_xor_sync(0xffffffffu, b, m);
    }
}
__device__ __forceinline__ float sqrt_pos(float x) {
    return x * rsqrtf(fmaxf(x, 1e-30f));
}

// ---------------- prep: WD, WB, Gram G, Mp[0]=I, Mp[1]=M ----------------
__global__ __launch_bounds__(256) void k_prep(const float* __restrict__ W,
                                              const float* __restrict__ Dm,
                                              const float* __restrict__ In,
                                              const float* __restrict__ M) {
    int bx = blockIdx.x, tid = threadIdx.x;
    if (bx < 128) {                       // WD
        int gid = bx * 256 + tid;
        int i = gid >> 10, j = gid & 1023;
        const float* wr = W + i * 1024;
        float a0 = 0.f, a1 = 0.f, a2 = 0.f, a3 = 0.f;
#pragma unroll 4
        for (int k = 0; k < 1024; k += 4) {
            a0 += wr[k + 0] * Dm[(k + 0) * D_ + j];
            a1 += wr[k + 1] * Dm[(k + 1) * D_ + j];
            a2 += wr[k + 2] * Dm[(k + 2) * D_ + j];
            a3 += wr[k + 3] * Dm[(k + 3) * D_ + j];
        }
        g_WD[gid] = (a0 + a1) + (a2 + a3);
    } else if (bx < 144) {                // WB
        int gid = (bx - 128) * 256 + tid;
        int i = gid >> 7, j = gid & 127;
        const float* wr = W + i * 1024;
        float a0 = 0.f, a1 = 0.f, a2 = 0.f, a3 = 0.f;
#pragma unroll 4
        for (int k = 0; k < 1024; k += 4) {
            a0 += wr[k + 0] * In[(k + 0) * S_ + j];
            a1 += wr[k + 1] * In[(k + 1) * S_ + j];
            a2 += wr[k + 2] * In[(k + 2) * S_ + j];
            a3 += wr[k + 3] * In[(k + 3) * S_ + j];
        }
        g_WB[gid] = (a0 + a1) + (a2 + a3);
    } else if (bx == 144) {               // Gram of W
        __shared__ float Wt[64 * 33];
        float acc[4] = {0.f, 0.f, 0.f, 0.f};
        for (int k0 = 0; k0 < 1024; k0 += 64) {
            __syncthreads();
            for (int lin = tid; lin < 2048; lin += 256) {
                int i = lin >> 6, kk = lin & 63;
                Wt[kk * 33 + i] = W[i * 1024 + k0 + kk];
            }
            __syncthreads();
#pragma unroll
            for (int q = 0; q < 4; q++) {
                int o = tid * 4 + q;
                int i = o >> 5, i2 = o & 31;
                float a = 0.f;
#pragma unroll 8
                for (int kk = 0; kk < 64; kk++) a += Wt[kk * 33 + i] * Wt[kk * 33 + i2];
                acc[q] += a;
            }
        }
#pragma unroll
        for (int q = 0; q < 4; q++) g_G[tid * 4 + q] = acc[q];
    } else if (bx < 153) {                // Mp[1] = M
        int base = (bx - 145) * 2048;
#pragma unroll
        for (int ii = 0; ii < 8; ii++) {
            int idx = base + ii * 256 + tid;
            g_Mp[16384 + idx] = M[idx];
        }
    } else {                              // Mp[0] = I, zero g_bad
        int base = (bx - 153) * 2048;
#pragma unroll
        for (int ii = 0; ii < 8; ii++) {
            int idx = base + ii * 256 + tid;
            g_Mp[idx] = ((idx >> 7) == (idx & 127)) ? 1.f : 0.f;
        }
        if (bx == 153 && tid == 0) g_bad = 0;
    }
}

// ---------------- gram2w: GD (bx0), GB (bx1), window-folded WD transpose (bx2,3) ----------------
__global__ __launch_bounds__(256) void k_gram2w() {
    int bx = blockIdx.x, tid = threadIdx.x;
    if (bx < 2) {
        const float* src = bx ? g_WB : g_WD;
        float* dst       = bx ? g_GB : g_GD;
        int K            = bx ? 128 : 1024;
        __shared__ float Wt[64 * 33];
        float acc[4] = {0.f, 0.f, 0.f, 0.f};
        for (int k0 = 0; k0 < K; k0 += 64) {
            __syncthreads();
            for (int lin = tid; lin < 2048; lin += 256) {
                int i = lin >> 6, kk = lin & 63;
                Wt[kk * 33 + i] = src[i * K + k0 + kk];
            }
            __syncthreads();
#pragma unroll
            for (int q = 0; q < 4; q++) {
                int o = tid * 4 + q;
                int i = o >> 5, i2 = o & 31;
                float a = 0.f;
#pragma unroll 8
                for (int kk = 0; kk < 64; kk++) a += Wt[kk * 33 + i] * Wt[kk * 33 + i2];
                acc[q] += a;
            }
        }
#pragma unroll
        for (int q = 0; q < 4; q++) dst[tid * 4 + q] = acc[q];
    } else {
        int j0 = (bx - 2) * 512;
        for (int idx = tid; idx < 16384; idx += 256) {
            int i2 = idx >> 9;
            int j = j0 + (idx & 511);
            float w = 0.5f * (1.0f - __cosf((float)j * 6.13592315154256491e-3f));
            g_WDwt[(size_t)j * 32 + i2] = g_WD[i2 * 1024 + j] * w;
        }
    }
}

// ---------------- k_go: G_O = Om Om^T ----------------
__global__ __launch_bounds__(256) void k_go(const float* __restrict__ Om) {
    int gid = blockIdx.x * 256 + threadIdx.x;     // 0..16383
    int i = gid >> 7, j = gid & 127;
    const float* ri = Om + (size_t)i * 1024;
    const float* rj = Om + (size_t)j * 1024;
    float a0 = 0.f, a1 = 0.f, a2 = 0.f, a3 = 0.f;
#pragma unroll 4
    for (int k = 0; k < 1024; k += 4) {
        a0 += ri[k + 0] * rj[k + 0];
        a1 += ri[k + 1] * rj[k + 1];
        a2 += ri[k + 2] * rj[k + 2];
        a3 += ri[k + 3] * rj[k + 3];
    }
    g_GO[gid] = (a0 + a1) + (a2 + a3);
}

// ---------------- k_omw: window-folded stacked Om [256][512] ----------------
__global__ void k_omw(const float* __restrict__ Om) {
    int idx = blockIdx.x * 256 + threadIdx.x;     // 0..131071
    int k = idx >> 9, j = idx & 511;
    float c = __cosf((float)j * 6.13592315154256491e-3f);
    float v;
    if (k < 128) v = Om[(size_t)k * 1024 + j] * (0.5f * (1.0f - c));
    else         v = Om[(size_t)(k - 128) * 1024 + j + 512] * (0.5f * (1.0f + c));
    g_Omw[idx] = v;
}

// ---------------- factors: per-row fd, fb via 32x32 quadforms; writes cd, cb, nb2 ----------------
__global__ __launch_bounds__(256) void k_factors(const float* __restrict__ control) {
    __shared__ float cs[64 * 32];
    __shared__ float Gs[32 * 33], GDs[32 * 33], GBs[32 * 33];

    int bx = blockIdx.x;
    int b = bx & 31, f0 = (bx >> 5) * 64;
    int tid = threadIdx.x;
    int w = tid >> 5, lane = tid & 31;

    for (int lin = tid; lin < 1024; lin += 256) {
        int i = lin >> 5, k = lin & 31;
        Gs[i * 33 + k]  = g_G[lin];
        GDs[i * 33 + k] = g_GD[lin];
        GBs[i * 33 + k] = g_GB[lin];
    }
#pragma unroll
    for (int p = 0; p < 8; p++) {
        int idx = tid + p * 256;
        int i = idx >> 6, f = idx & 63;
        cs[f * 32 + i] = control[(size_t)b * 32768 + i * 1024 + f0 + f];
    }
    __syncthreads();

#pragma unroll
    for (int p = 0; p < 8; p++) {
        int f = w * 8 + p;
        float c = cs[f * 32 + lane];
        float gd = 0.f, gdd = 0.f, gbb = 0.f;
#pragma unroll
        for (int k = 0; k < 32; k++) {
            float ck = cs[f * 32 + k];
            gd  += Gs[lane * 33 + k] * ck;
            gdd += GDs[lane * 33 + k] * ck;
            gbb += GBs[lane * 33 + k] * ck;
        }
        float nv2 = c * c, nx2 = c * gd;
        warp_sum2(nv2, nx2);
        float tsd = c * gdd, tsb = c * gbb;
        warp_sum2(tsd, tsb);

        float nv = sqrt_pos(nv2), nx = sqrt_pos(nx2);
        float facp = __fdividef(fminf(nx, nv), nx + EPS);
        float nproj = facp * nx;
        float nxd = facp * sqrt_pos(tsd);
        float nxb = facp * sqrt_pos(tsb);
        float fd = facp * __fdividef(fminf(nxd, nproj), nxd + EPS);
        float fb = facp * __fdividef(fminf(nxb, nproj), nxb + EPS);

        int r = (f0 + f) * 32 + b;
        g_cd[(size_t)r * 32 + lane] = fd * c;
        g_cb[(size_t)r * 32 + lane] = fb * c;
        if (lane == 0) g_nb2[r] = fb * fb * tsb;
    }
}

// ---------------- k_olay: out = windowed OLA of the yd term (rank-32 on the fly) ----
__global__ __launch_bounds__(512) void k_olay(float* __restrict__ out) {
    __shared__ __align__(16) float cds[65 * 32];

    int bx = blockIdx.x;
    int b = bx & 31, f0 = (bx >> 5) * 64;
    int tid = threadIdx.x;

    u64 w1p[16], w0p[16];
    const u64* r1p = (const u64*)&g_WDwt[(size_t)tid * 32];
    const u64* r0p = (const u64*)&g_WDwt[(size_t)(tid + 512) * 32];
#pragma unroll
    for (int m = 0; m < 16; m++) { w1p[m] = r1p[m]; w0p[m] = r0p[m]; }

    for (int idx = tid; idx < 65 * 8; idx += 512) {
        int k = idx >> 3, quad = idx & 7;
        int f = f0 - 1 + k;
        float4 v = make_float4(0.f, 0.f, 0.f, 0.f);
        if (f >= 0) v = *(const float4*)&g_cd[((size_t)(f * 32 + b)) * 32 + quad * 4];
        *(float4*)&cds[k * 32 + quad * 4] = v;
    }
    __syncthreads();

    size_t obase = (size_t)b * 524288 + (size_t)f0 * 512 + tid;
#pragma unroll 4
    for (int k = 0; k < 64; k++) {
        const u64* c1 = (const u64*)&cds[(k + 1) * 32];
        const u64* c0 = (const u64*)&cds[k * 32];
        u64 a0 = 0, a1 = 0;
#pragma unroll
        for (int m = 0; m < 16; m++) {
            fma2(a0, w1p[m], c1[m]);
            fma2(a1, w0p[m], c0[m]);
        }
        float2 u0 = upk2(a0), u1 = upk2(a1);
        out[obase + (size_t)k * 512] = (u0.x + u0.y) + (u1.x + u1.y);
    }
}

// ---------------- k_yb: g_yb = cb[32768,32] @ WB[32,128] ----------------
__global__ __launch_bounds__(256) void k_yb() {
    __shared__ __align__(16) float ats[64 * 32];
    __shared__ __align__(16) float bts[32 * 128];
    int r0 = blockIdx.x * 64;
    int tid = threadIdx.x;

    const float4* A4 = (const float4*)(g_cb + (size_t)r0 * 32);
    ((float4*)ats)[tid] = A4[tid];
    ((float4*)ats)[tid + 256] = A4[tid + 256];
#pragma unroll
    for (int p = 0; p < 4; p++) {
        int idx = tid + p * 256;
        int i = idx >> 5, q = idx & 31;
        *(float4*)&bts[i * 128 + q * 4] = *(const float4*)&g_WB[i * 128 + q * 4];
    }
    __syncthreads();

    int tm = tid >> 4, tn = tid & 15;
    u64 acc[4][4];
#pragma unroll
    for (int i = 0; i < 4; i++)
#pragma unroll
        for (int p = 0; p < 4; p++) acc[i][p] = 0;

#pragma unroll
    for (int k = 0; k < 32; k++) {
        const u64* br = (const u64*)&bts[k * 128 + tn * 8];
        u64 b0 = br[0], b1 = br[1], b2 = br[2], b3 = br[3];
#pragma unroll
        for (int p = 0; p < 4; p++) {
            float av = ats[(tm * 4 + p) * 32 + k];
            u64 a2 = pk2(av, av);
            fma2(acc[p][0], a2, b0);
            fma2(acc[p][1], a2, b1);
            fma2(acc[p][2], a2, b2);
            fma2(acc[p][3], a2, b3);
        }
    }
#pragma unroll
    for (int p = 0; p < 4; p++) {
        int row = r0 + tm * 4 + p;
        float2 c0 = upk2(acc[p][0]), c1 = upk2(acc[p][1]);
        float2 c2 = upk2(acc[p][2]), c3 = upk2(acc[p][3]);
        float4* dst = (float4*)&g_yb[(size_t)row * 128 + tn * 8];
        dst[0] = make_float4(c0.x, c0.y, c1.x, c1.y);
        dst[1] = make_float4(c2.x, c2.y, c3.x, c3.y);
    }
}

// ---------------- k_pow: Mp[k] = Mp[k/2] @ Mp[k-k/2] ----------------
__global__ __launch_bounds__(256) void k_pow(int kstart) {
    int k = kstart + blockIdx.y;
    int a = k >> 1, b2 = k - a;
    const float* A  = g_Mp + (size_t)a  * 16384;
    const float* Bp = g_Mp + (size_t)b2 * 16384;
    float* O = g_Mp + (size_t)k * 16384;

    __shared__ float Ash[16][128];
    int r0 = blockIdx.x * 16;
    int tid = threadIdx.x;
#pragma unroll
    for (int q = 0; q < 8; q++) {
        int idx = q * 256 + tid;
        Ash[idx >> 7][idx & 127] = A[r0 * 128 + idx];
    }
    __syncthreads();

    int rl = tid >> 4;
    int c0 = (tid & 15) * 8;
    u64 acc[4] = {0, 0, 0, 0};
    for (int m = 0; m < 128; m++) {
        float av = Ash[rl][m];
        u64 a2 = pk2(av, av);
        const u64* brow = (const u64*)(Bp + m * 128 + c0);
        fma2(acc[0], a2, brow[0]);
        fma2(acc[1], a2, brow[1]);
        fma2(acc[2], a2, brow[2]);
        fma2(acc[3], a2, brow[3]);
    }
    float* orow = O + (r0 + rl) * 128 + c0;
#pragma unroll
    for (int p = 0; p < 4; p++) {
        float2 f = upk2(acc[p]);
        orow[2 * p] = f.x; orow[2 * p + 1] = f.y;
    }
}

// ---------------- k_wbmp: WBMp[i] = WB @ Mp[15-i] ----------------
__global__ __launch_bounds__(256) void k_wbmp() {
    int i = blockIdx.x;
    const float* Mw = g_Mp + (size_t)(15 - i) * 16384;
    __shared__ float wbs[32 * 132];
    int tid = threadIdx.x;
#pragma unroll
    for (int p = 0; p < 16; p++) {
        int idx = tid + p * 256;
        int row = idx >> 7, k = idx & 127;
        wbs[row * 132 + k] = g_WB[row * 128 + k];
    }
    __syncthreads();

    int row = tid >> 3, j0 = (tid & 7) * 16;
    u64 acc[8] = {0, 0, 0, 0, 0, 0, 0, 0};
    for (int k = 0; k < 128; k++) {
        float wv = wbs[row * 132 + k];
        u64 w2 = pk2(wv, wv);
        const u64* mr = (const u64*)(Mw + k * 128 + j0);
#pragma unroll
        for (int p = 0; p < 8; p++) fma2(acc[p], w2, mr[p]);
    }
    float* o = g_WBMp + ((size_t)i * 32 + row) * 128 + j0;
#pragma unroll
    for (int p = 0; p < 8; p++) {
        float2 f = upk2(acc[p]);
        o[2 * p] = f.x; o[2 * p + 1] = f.y;
    }
}

// ---------------- k_rcg: rc[c*32+b] = sum_i cb[(c*16+i)*32+b] @ WBMp[i] ----------------
__global__ __launch_bounds__(256) void k_rcg() {
    __shared__ __align__(16) float ats[64 * 32];
    __shared__ __align__(16) float bts[32 * 128];
    int r0 = blockIdx.x * 64;
    int tid = threadIdx.x;
    int tm = tid >> 4, tn = tid & 15;

    u64 acc[4][4];
#pragma unroll
    for (int ii = 0; ii < 4; ii++)
#pragma unroll
        for (int p = 0; p < 4; p++) acc[ii][p] = 0;

    for (int i = 0; i < W_; i++) {
        __syncthreads();
#pragma unroll
        for (int p = 0; p < 2; p++) {
            int idx = tid + p * 256;
            int m = idx >> 3, quad = idx & 7;
            int cb = r0 + m, c = cb >> 5, b = cb & 31;
            size_t fr = (size_t)((c * W_ + i) * 32 + b);
            ((float4*)ats)[idx] = *(const float4*)&g_cb[fr * 32 + quad * 4];
        }
#pragma unroll
        for (int p = 0; p < 4; p++) {
            int idx = tid + p * 256;
            int ii = idx >> 5, q = idx & 31;
            *(float4*)&bts[ii * 128 + q * 4] =
                *(const float4*)&g_WBMp[((size_t)i * 32 + ii) * 128 + q * 4];
        }
        __syncthreads();
#pragma unroll
        for (int k = 0; k < 32; k++) {
            const u64* br = (const u64*)&bts[k * 128 + tn * 8];
            u64 b0 = br[0], b1 = br[1], b2 = br[2], b3 = br[3];
#pragma unroll
            for (int p = 0; p < 4; p++) {
                float av = ats[(tm * 4 + p) * 32 + k];
                u64 a2 = pk2(av, av);
                fma2(acc[p][0], a2, b0);
                fma2(acc[p][1], a2, b1);
                fma2(acc[p][2], a2, b2);
                fma2(acc[p][3], a2, b3);
            }
        }
    }
#pragma unroll
    for (int p = 0; p < 4; p++) {
        int row = r0 + tm * 4 + p;
        float2 c0 = upk2(acc[p][0]), c1 = upk2(acc[p][1]);
        float2 c2 = upk2(acc[p][2]), c3 = upk2(acc[p][3]);
        float4* dst = (float4*)&g_rc[(size_t)row * 128 + tn * 8];
        dst[0] = make_float4(c0.x, c0.y, c1.x, c1.y);
        dst[1] = make_float4(c2.x, c2.y, c3.x, c3.y);
    }
}

// ---------------- k_chain: S_{c+1} = S_c @ Mp[16] + r_c ----------------
__global__ __launch_bounds__(128) void k_chain() {
    int b = blockIdx.x;
    int j = threadIdx.x;
    __shared__ __align__(16) float ssh[2][128];

    u64 mcol[64];
    const float* M16 = g_Mp + (size_t)16 * 16384;
#pragma unroll
    for (int m = 0; m < 64; m++)
        mcol[m] = pk2(M16[(2 * m) * 128 + j], M16[(2 * m + 1) * 128 + j]);

    ssh[0][j] = 0.f;
    g_S[(0 * 32 + b) * 128 + j] = 0.f;
    __syncthreads();

    for (int c = 0; c < NC_ - 1; c++) {
        int cur = c & 1;
        const u64* sv = (const u64*)ssh[cur];
        u64 a0 = 0, a1 = 0, a2 = 0, a3 = 0;
#pragma unroll
        for (int m = 0; m < 64; m += 4) {
            fma2(a0, mcol[m + 0], sv[m + 0]);
            fma2(a1, mcol[m + 1], sv[m + 1]);
            fma2(a2, mcol[m + 2], sv[m + 2]);
            fma2(a3, mcol[m + 3], sv[m + 3]);
        }
        float2 u0 = upk2(a0), u1 = upk2(a1), u2 = upk2(a2), u3 = upk2(a3);
        float y = ((u0.x + u0.y) + (u1.x + u1.y)) + ((u2.x + u2.y) + (u3.x + u3.y));
        float sn = y + g_rc[((size_t)(c * 32 + b)) * 128 + j];
        ssh[cur ^ 1][j] = sn;
        g_S[((c + 1) * 32 + b) * 128 + j] = sn;
        __syncthreads();
    }
}

// ---------------- k_expand: within-chunk linear steps -> x_t ----------------
__global__ __launch_bounds__(128) void k_expand() {
    int c = blockIdx.x >> 5;
    int b = blockIdx.x & 31;
    int j = threadIdx.x;
    __shared__ __align__(16) float ssh[2][128];

    u64 mcol[64];
    const float* M1 = g_Mp + (size_t)16384;
#pragma unroll
    for (int m = 0; m < 64; m++)
        mcol[m] = pk2(M1[(2 * m) * 128 + j], M1[(2 * m + 1) * 128 + j]);

    ssh[0][j] = g_S[((size_t)(c * 32 + b)) * 128 + j];
    __syncthreads();

    for (int i = 0; i < W_; i++) {
        int t = c * W_ + i;
        int cur = i & 1;
        const u64* sv = (const u64*)ssh[cur];
        u64 a0 = 0, a1 = 0, a2 = 0, a3 = 0;
#pragma unroll
        for (int m = 0; m < 64; m += 4) {
            fma2(a0, mcol[m + 0], sv[m + 0]);
            fma2(a1, mcol[m + 1], sv[m + 1]);
            fma2(a2, mcol[m + 2], sv[m + 2]);
            fma2(a3, mcol[m + 3], sv[m + 3]);
        }
        float2 u0 = upk2(a0), u1 = upk2(a1), u2 = upk2(a2), u3 = upk2(a3);
        float y = ((u0.x + u0.y) + (u1.x + u1.y)) + ((u2.x + u2.y) + (u3.x + u3.y));
        size_t row = (size_t)(t * 32 + b) * 128;
        g_x[row + j] = y;
        float sn = y + g_yb[row + j];
        ssh[cur ^ 1][j] = sn;
        __syncthreads();
    }
}

// ---------------- k_fac: exact factors from speculative x; writes sp, nsp, bad ----------------
__global__ __launch_bounds__(256) void k_fac() {
    int tid = threadIdx.x;
    int warp = tid >> 5, lane = tid & 31;
    int r = blockIdx.x * 8 + warp;
    int t = r >> 5;

    float4 x4 = ((const float4*)(g_x + (size_t)r * 128))[lane];

    float4 s4 = make_float4(0.f, 0.f, 0.f, 0.f);
    if (t > 0) {
        int pr = r - 32;
        float4 xp = ((const float4*)(g_x + (size_t)pr * 128))[lane];
        float4 bp = ((const float4*)(g_yb + (size_t)pr * 128))[lane];
        s4 = make_float4(xp.x + bp.x, xp.y + bp.y, xp.z + bp.z, xp.w + bp.w);
    }

    float px = x4.x * x4.x + x4.y * x4.y + x4.z * x4.z + x4.w * x4.w;
    float ps = s4.x * s4.x + s4.y * s4.y + s4.z * s4.z + s4.w * s4.w;
    warp_sum2(px, ps);
    float nxs = sqrt_pos(px), ns = sqrt_pos(ps);
    float fac = __fdividef(fminf(nxs, ns), nxs + EPS);

    float4 sp4 = make_float4(fac * x4.x, fac * x4.y, fac * x4.z, fac * x4.w);
    ((float4*)(g_sp + (size_t)r * 128))[lane] = sp4;
    if (lane == 0) {
        g_nsp[r] = fac * nxs;
        if (px > ps) g_bad = 1;
    }
}

// ---------------- k_repair: exact sequential scan, runs only if g_bad ----------------
__global__ __launch_bounds__(512) void k_repair(const float* __restrict__ A) {
    if (g_bad == 0) return;

    __shared__ __align__(16) float s_sh[S_];
    __shared__ float part[512];
    __shared__ float red1[4], red2[4];

    int b = blockIdx.x;
    int tid = threadIdx.x;
    int q = tid >> 7, j = tid & 127;
    int warp = tid >> 5, lane = tid & 31;

    u64 apk[16];
#pragma unroll
    for (int m = 0; m < 16; m++)
        apk[m] = pk2(A[(q * 32 + 2 * m) * 128 + j], A[(q * 32 + 2 * m + 1) * 128 + j]);

    if (tid < 128) s_sh[tid] = 0.f;
    float ns = 0.f;
    float binp_cur = 0.f, binp_nxt = 0.f;
    float nb2_cur = 0.f, nb2_nxt = 0.f;
    if (tid < 128) {
        binp_cur = g_yb[(size_t)b * 128 + j];
        nb2_cur = g_nb2[b];
    }
    __syncthreads();

    for (int t = 0; t < F_; t++) {
        if (tid < 128 && t + 1 < F_) {
            size_t rn = (size_t)((t + 1) * 32 + b);
            binp_nxt = g_yb[rn * 128 + j];
            nb2_nxt = g_nb2[rn];
        }
        u64 a0 = 0, a1 = 0, a2 = 0, a3 = 0;
#pragma unroll
        for (int m = 0; m < 16; m += 4) {
            fma2(a0, apk[m + 0], *(const u64*)&s_sh[q * 32 + 2 * m + 0]);
            fma2(a1, apk[m + 1], *(const u64*)&s_sh[q * 32 + 2 * m + 2]);
            fma2(a2, apk[m + 2], *(const u64*)&s_sh[q * 32 + 2 * m + 4]);
            fma2(a3, apk[m + 3], *(const u64*)&s_sh[q * 32 + 2 * m + 6]);
        }
        float2 u0 = upk2(a0), u1 = upk2(a1), u2 = upk2(a2), u3 = upk2(a3);
        part[tid] = ((u0.x + u0.y) + (u1.x + u1.y)) + ((u2.x + u2.y) + (u3.x + u3.y));
        __syncthreads();

        float xs = 0.f;
        if (tid < 128) {
            xs = (part[j] + part[128 + j]) + (part[256 + j] + part[384 + j]);
            float px = xs * xs, pxb = xs * binp_cur;
            warp_sum2(px, pxb);
            if (lane == 0) { red1[warp] = px; red2[warp] = pxb; }
        }
        __syncthreads();

        if (tid < 128) {
            float nxs2 = (red1[0] + red1[1]) + (red1[2] + red1[3]);
            float xb   = (red2[0] + red2[1]) + (red2[2] + red2[3]);
            float nxs = sqrt_pos(nxs2);
            float fac = __fdividef(fminf(nxs, ns), nxs + EPS);
            float sp = fac * xs;
            g_sp[(size_t)(t * 32 + b) * 128 + j] = sp;
            if (tid == 0) g_nsp[t * 32 + b] = fac * nxs;
            s_sh[j] = sp + binp_cur;
            ns = sqrt_pos(fac * fac * nxs2 + 2.f * fac * xb + nb2_cur);
            binp_cur = binp_nxt;
            nb2_cur = nb2_nxt;
        }
        __syncthreads();
    }
}

// ---------------- k_fcq: fc per row via quadform sp^T G_O sp (always runs, after repair) ----------------
__global__ __launch_bounds__(256) void k_fcq() {
    __shared__ float sps[8][132];
    int tid = threadIdx.x, warp = tid >> 5, lane = tid & 31;

#pragma unroll 1
    for (int p = 0; p < 8; p++) {
        int r = blockIdx.x * 64 + warp * 8 + p;
        float4 sp4 = ((const float4*)(g_sp + (size_t)r * 128))[lane];
        *(float4*)&sps[warp][lane * 4] = sp4;
        __syncwarp();

        float4 y = make_float4(0.f, 0.f, 0.f, 0.f);
#pragma unroll 2
        for (int k = 0; k < 128; k++) {
            float sk = sps[warp][k];
            float4 g = *(const float4*)&g_GO[k * 128 + lane * 4];
            y.x += sk * g.x; y.y += sk * g.y; y.z += sk * g.z; y.w += sk * g.w;
        }
        float q = y.x * sp4.x + y.y * sp4.y + y.z * sp4.z + y.w * sp4.w;
        float nxc2 = warp_sum(q);
        float nxc = sqrt_pos(nxc2);
        if (lane == 0)
            g_fc[r] = __fdividef(fminf(nxc, g_nsp[r]), nxc + EPS);
        __syncwarp();
    }
}

// ---------------- k_gemm2: out += (fc1*sp[r1] || fc0*sp[r0]) @ Omw  (K=256, fused OLA) ----------------
#define KC 32
__global__ __launch_bounds__(256) void k_gemm2(float* __restrict__ out) {
    __shared__ float As[KC][128];
    __shared__ float Bs[KC][128];
    __shared__ float fc1s[128], fc0s[128];

    int m0 = blockIdx.y * 128, n0 = blockIdx.x * 128;
    int tid = threadIdx.x;
    int tm = tid >> 4, tn = tid & 15;

    if (tid < 128) {
        fc1s[tid] = g_fc[m0 + tid];
        fc0s[tid] = (m0 + tid >= 32) ? g_fc[m0 + tid - 32] : 0.f;
    }

    u64 acc2[8][4];
#pragma unroll
    for (int i = 0; i < 8; i++)
#pragma unroll
        for (int p = 0; p < 4; p++) acc2[i][p] = 0;

    const float4* A4 = (const float4*)g_sp;
    const float4* B4 = (const float4*)g_Omw;

    for (int kc = 0; kc < 256; kc += KC) {
        __syncthreads();
#pragma unroll
        for (int ii = 0; ii < 4; ii++) {
            int slot = tid + ii * 256;
            int m = slot >> 3, k4 = slot & 7;
            float4 v;
            float sc;
            if (kc < 128) {
                v = A4[(size_t)(m0 + m) * 32 + (kc >> 2) + k4];
                sc = fc1s[m];
            } else {
                int r2 = m0 + m - 32;
                if (r2 >= 0) {
                    v = A4[(size_t)r2 * 32 + ((kc - 128) >> 2) + k4];
                    sc = fc0s[m];
                } else {
                    v = make_float4(0.f, 0.f, 0.f, 0.f);
                    sc = 0.f;
                }
            }
            As[k4 * 4 + 0][m] = v.x * sc;
            As[k4 * 4 + 1][m] = v.y * sc;
            As[k4 * 4 + 2][m] = v.z * sc;
            As[k4 * 4 + 3][m] = v.w * sc;
        }
#pragma unroll
        for (int ii = 0; ii < 4; ii++) {
            int slot = tid + ii * 256;
            int k = slot >> 5, n4 = slot & 31;
            float4 v = B4[(size_t)(kc + k) * 128 + (n0 >> 2) + n4];
            *((float4*)&Bs[k][n4 * 4]) = v;
        }
        __syncthreads();
#pragma unroll
        for (int k = 0; k < KC; k++) {
            float4 af0 = *(const float4*)&As[k][tm * 8];
            float4 af1 = *(const float4*)&As[k][tm * 8 + 4];
            u64 bp0 = *(const u64*)&Bs[k][tn * 8 + 0];
            u64 bp1 = *(const u64*)&Bs[k][tn * 8 + 2];
            u64 bp2 = *(const u64*)&Bs[k][tn * 8 + 4];
            u64 bp3 = *(const u64*)&Bs[k][tn * 8 + 6];
            u64 ad[8];
            ad[0] = pk2(af0.x, af0.x); ad[1] = pk2(af0.y, af0.y);
            ad[2] = pk2(af0.z, af0.z); ad[3] = pk2(af0.w, af0.w);
            ad[4] = pk2(af1.x, af1.x); ad[5] = pk2(af1.y, af1.y);
            ad[6] = pk2(af1.z, af1.z); ad[7] = pk2(af1.w, af1.w);
#pragma unroll
            for (int mi = 0; mi < 8; mi++) {
                fma2(acc2[mi][0], ad[mi], bp0);
                fma2(acc2[mi][1], ad[mi], bp1);
                fma2(acc2[mi][2], ad[mi], bp2);
                fma2(acc2[mi][3], ad[mi], bp3);
            }
        }
    }

#pragma unroll
    for (int mi = 0; mi < 8; mi++) {
        int row = m0 + tm * 8 + mi;
        int b = row & 31, f = row >> 5;
        float2 c0 = upk2(acc2[mi][0]), c1 = upk2(acc2[mi][1]);
        float2 c2 = upk2(acc2[mi][2]), c3 = upk2(acc2[mi][3]);
        float4* dst = (float4*)(out + (size_t)b * 524288 + (size_t)f * 512 + n0 + tn * 8);
        float4 d0 = dst[0], d1 = dst[1];
        dst[0] = make_float4(d0.x + c0.x, d0.y + c0.y, d0.z + c1.x, d0.w + c1.y);
        dst[1] = make_float4(d1.x + c2.x, d1.y + c2.y, d1.z + c3.x, d1.w + c3.y);
    }
}

extern "C" void kernel_launch(void* const* d_in, const int* in_sizes, int n_in,
                              void* d_out, int out_size) {
    const float* control  = (const float*)d_in[0];
    const float* proj_w   = (const float*)d_in[1];
    const float* state_m  = (const float*)d_in[2];
    const float* input_m  = (const float*)d_in[3];
    const float* output_m = (const float*)d_in[4];
    const float* direct_m = (const float*)d_in[5];
    float* out = (float*)d_out;

    k_prep<<<161, 256>>>(proj_w, direct_m, input_m, state_m);  // #1
    k_gram2w<<<4, 256>>>();                                    // #2
    k_factors<<<512, 256>>>(control);                          // #3
    k_olay<<<512, 512>>>(out);                                 // #4  <- profiled
    k_go<<<64, 256>>>(output_m);                               // #5
    k_omw<<<512, 256>>>(output_m);                             // #6
    k_pow<<<dim3(8, 1), 256>>>(2);                             // #7
    k_pow<<<dim3(8, 2), 256>>>(3);                             // #8
    k_pow<<<dim3(8, 4), 256>>>(5);                             // #9
    k_pow<<<dim3(8, 8), 256>>>(9);                             // #10
    k_wbmp<<<16, 256>>>();                                     // #11
    k_yb<<<512, 256>>>();                                      // #12
    k_rcg<<<32, 256>>>();                                      // #13
    k_chain<<<32, 128>>>();                                    // #14
    k_expand<<<NC_ * 32, 128>>>();                             // #15
    k_fac<<<4096, 256>>>();                                    // #16
    k_repair<<<32, 512>>>(state_m);                            // #17
    k_fcq<<<512, 256>>>();                                     // #18
    k_gemm2<<<dim3(4, 256), 256>>>(out);                       // #19
}

// round 15
// speedup vs baseline: 1.0374x; 1.0374x over previous
#include <cuda_runtime.h>
#include <math.h>

#define EPS 1e-8f
#define B_   32
#define CPD_ 32
#define F_   1024
#define D_   1024
#define S_   128
#define BF_  (B_*F_)        // 32768
#define W_   16             // chunk width
#define NC_  64             // number of chunks

typedef unsigned long long u64;

// ---------------- device scratch ----------------
__device__ float g_WD[CPD_*D_];        // W @ direct   [32][1024]
__device__ float g_WB[CPD_*S_];        // W @ input    [32][128]
__device__ float g_G[CPD_*CPD_];       // W W^T
__device__ float g_GD[CPD_*CPD_];      // WD WD^T
__device__ float g_GB[CPD_*CPD_];      // WB WB^T
__device__ float g_GO[S_*S_];          // Om Om^T
__device__ float g_WDwt[D_*CPD_];      // window-folded WD transpose [j][i]
__device__ float g_Omw[256*512];       // window-folded stacked Om [256][512]
__device__ float g_cd[(size_t)BF_*CPD_]; // fd-scaled control rows [r][32]
__device__ float g_cb[(size_t)BF_*CPD_]; // fb-scaled control rows [r][32]
__device__ float g_yb[(size_t)BF_*S_]; // b rows [f*32+b][128]
__device__ float g_nb2[BF_];           // ||b||^2 per frame
__device__ float g_Mp[17*S_*S_];       // M^0..M^16
__device__ float g_WBMp[W_*CPD_*S_];   // WB @ M^(15-i), i=0..15
__device__ float g_rc[NC_*B_*S_];      // chunk residuals
__device__ float g_S[NC_*B_*S_];       // chunk-start states
__device__ float g_x[(size_t)BF_*S_];  // speculative x_t = s_t M; later reused as Y = sp @ G_O
__device__ float g_sp[(size_t)BF_*S_]; // s'_t rows
__device__ float g_nsp[BF_];           // ||s'_t||
__device__ float g_fc[BF_];            // c factor
__device__ int   g_bad;                // clamp-active flag

// ---------------- f32x2 helpers ----------------
__device__ __forceinline__ void fma2(u64 &acc, u64 a, u64 b) {
    asm("fma.rn.f32x2 %0, %1, %2, %0;" : "+l"(acc) : "l"(a), "l"(b));
}
__device__ __forceinline__ u64 pk2(float lo, float hi) {
    u64 r; asm("mov.b64 %0, {%1, %2};" : "=l"(r) : "f"(lo), "f"(hi)); return r;
}
__device__ __forceinline__ float2 upk2(u64 v) {
    float lo, hi; asm("mov.b64 {%0, %1}, %2;" : "=f"(lo), "=f"(hi) : "l"(v));
    return make_float2(lo, hi);
}
__device__ __forceinline__ float warp_sum(float v) {
#pragma unroll
    for (int m = 16; m > 0; m >>= 1) v += __shfl_xor_sync(0xffffffffu, v, m);
    return v;
}
__device__ __forceinline__ void warp_sum2(float &a, float &b) {
#pragma unroll
    for (int m = 16; m > 0; m >>= 1) {
        a += __shfl_xor_sync(0xffffffffu, a, m);
        b += __shfl_xor_sync(0xffffffffu, b, m);
    }
}
__device__ __forceinline__ float sqrt_pos(float x) {
    return x * rsqrtf(fmaxf(x, 1e-30f));
}

// ---------------- prep: WD, WB, Gram G, Mp[0]=I, Mp[1]=M ----------------
__global__ __launch_bounds__(256) void k_prep(const float* __restrict__ W,
                                              const float* __restrict__ Dm,
                                              const float* __restrict__ In,
                                              const float* __restrict__ M) {
    int bx = blockIdx.x, tid = threadIdx.x;
    if (bx < 128) {                       // WD
        int gid = bx * 256 + tid;
        int i = gid >> 10, j = gid & 1023;
        const float* wr = W + i * 1024;
        float a0 = 0.f, a1 = 0.f, a2 = 0.f, a3 = 0.f;
#pragma unroll 4
        for (int k = 0; k < 1024; k += 4) {
            a0 += wr[k + 0] * Dm[(k + 0) * D_ + j];
            a1 += wr[k + 1] * Dm[(k + 1) * D_ + j];
            a2 += wr[k + 2] * Dm[(k + 2) * D_ + j];
            a3 += wr[k + 3] * Dm[(k + 3) * D_ + j];
        }
        g_WD[gid] = (a0 + a1) + (a2 + a3);
    } else if (bx < 144) {                // WB
        int gid = (bx - 128) * 256 + tid;
        int i = gid >> 7, j = gid & 127;
        const float* wr = W + i * 1024;
        float a0 = 0.f, a1 = 0.f, a2 = 0.f, a3 = 0.f;
#pragma unroll 4
        for (int k = 0; k < 1024; k += 4) {
            a0 += wr[k + 0] * In[(k + 0) * S_ + j];
            a1 += wr[k + 1] * In[(k + 1) * S_ + j];
            a2 += wr[k + 2] * In[(k + 2) * S_ + j];
            a3 += wr[k + 3] * In[(k + 3) * S_ + j];
        }
        g_WB[gid] = (a0 + a1) + (a2 + a3);
    } else if (bx == 144) {               // Gram of W
        __shared__ float Wt[64 * 33];
        float acc[4] = {0.f, 0.f, 0.f, 0.f};
        for (int k0 = 0; k0 < 1024; k0 += 64) {
            __syncthreads();
            for (int lin = tid; lin < 2048; lin += 256) {
                int i = lin >> 6, kk = lin & 63;
                Wt[kk * 33 + i] = W[i * 1024 + k0 + kk];
            }
            __syncthreads();
#pragma unroll
            for (int q = 0; q < 4; q++) {
                int o = tid * 4 + q;
                int i = o >> 5, i2 = o & 31;
                float a = 0.f;
#pragma unroll 8
                for (int kk = 0; kk < 64; kk++) a += Wt[kk * 33 + i] * Wt[kk * 33 + i2];
                acc[q] += a;
            }
        }
#pragma unroll
        for (int q = 0; q < 4; q++) g_G[tid * 4 + q] = acc[q];
    } else if (bx < 153) {                // Mp[1] = M
        int base = (bx - 145) * 2048;
#pragma unroll
        for (int ii = 0; ii < 8; ii++) {
            int idx = base + ii * 256 + tid;
            g_Mp[16384 + idx] = M[idx];
        }
    } else {                              // Mp[0] = I, zero g_bad
        int base = (bx - 153) * 2048;
#pragma unroll
        for (int ii = 0; ii < 8; ii++) {
            int idx = base + ii * 256 + tid;
            g_Mp[idx] = ((idx >> 7) == (idx & 127)) ? 1.f : 0.f;
        }
        if (bx == 153 && tid == 0) g_bad = 0;
    }
}

// ---------------- gram2w: GD (bx0), GB (bx1), window-folded WD transpose (bx2,3) ----------------
__global__ __launch_bounds__(256) void k_gram2w() {
    int bx = blockIdx.x, tid = threadIdx.x;
    if (bx < 2) {
        const float* src = bx ? g_WB : g_WD;
        float* dst       = bx ? g_GB : g_GD;
        int K            = bx ? 128 : 1024;
        __shared__ float Wt[64 * 33];
        float acc[4] = {0.f, 0.f, 0.f, 0.f};
        for (int k0 = 0; k0 < K; k0 += 64) {
            __syncthreads();
            for (int lin = tid; lin < 2048; lin += 256) {
                int i = lin >> 6, kk = lin & 63;
                Wt[kk * 33 + i] = src[i * K + k0 + kk];
            }
            __syncthreads();
#pragma unroll
            for (int q = 0; q < 4; q++) {
                int o = tid * 4 + q;
                int i = o >> 5, i2 = o & 31;
                float a = 0.f;
#pragma unroll 8
                for (int kk = 0; kk < 64; kk++) a += Wt[kk * 33 + i] * Wt[kk * 33 + i2];
                acc[q] += a;
            }
        }
#pragma unroll
        for (int q = 0; q < 4; q++) dst[tid * 4 + q] = acc[q];
    } else {
        int j0 = (bx - 2) * 512;
        for (int idx = tid; idx < 16384; idx += 256) {
            int i2 = idx >> 9;
            int j = j0 + (idx & 511);
            float w = 0.5f * (1.0f - __cosf((float)j * 6.13592315154256491e-3f));
            g_WDwt[(size_t)j * 32 + i2] = g_WD[i2 * 1024 + j] * w;
        }
    }
}

// ---------------- k_go: G_O = Om Om^T ----------------
__global__ __launch_bounds__(256) void k_go(const float* __restrict__ Om) {
    int gid = blockIdx.x * 256 + threadIdx.x;     // 0..16383
    int i = gid >> 7, j = gid & 127;
    const float* ri = Om + (size_t)i * 1024;
    const float* rj = Om + (size_t)j * 1024;
    float a0 = 0.f, a1 = 0.f, a2 = 0.f, a3 = 0.f;
#pragma unroll 4
    for (int k = 0; k < 1024; k += 4) {
        a0 += ri[k + 0] * rj[k + 0];
        a1 += ri[k + 1] * rj[k + 1];
        a2 += ri[k + 2] * rj[k + 2];
        a3 += ri[k + 3] * rj[k + 3];
    }
    g_GO[gid] = (a0 + a1) + (a2 + a3);
}

// ---------------- k_omw: window-folded stacked Om [256][512] ----------------
__global__ void k_omw(const float* __restrict__ Om) {
    int idx = blockIdx.x * 256 + threadIdx.x;     // 0..131071
    int k = idx >> 9, j = idx & 511;
    float c = __cosf((float)j * 6.13592315154256491e-3f);
    float v;
    if (k < 128) v = Om[(size_t)k * 1024 + j] * (0.5f * (1.0f - c));
    else         v = Om[(size_t)(k - 128) * 1024 + j + 512] * (0.5f * (1.0f + c));
    g_Omw[idx] = v;
}

// ---------------- factors: per-row fd, fb via 32x32 quadforms; writes cd, cb, nb2 ----------------
__global__ __launch_bounds__(256) void k_factors(const float* __restrict__ control) {
    __shared__ float cs[64 * 32];
    __shared__ float Gs[32 * 33], GDs[32 * 33], GBs[32 * 33];

    int bx = blockIdx.x;
    int b = bx & 31, f0 = (bx >> 5) * 64;
    int tid = threadIdx.x;
    int w = tid >> 5, lane = tid & 31;

    for (int lin = tid; lin < 1024; lin += 256) {
        int i = lin >> 5, k = lin & 31;
        Gs[i * 33 + k]  = g_G[lin];
        GDs[i * 33 + k] = g_GD[lin];
        GBs[i * 33 + k] = g_GB[lin];
    }
#pragma unroll
    for (int p = 0; p < 8; p++) {
        int idx = tid + p * 256;
        int i = idx >> 6, f = idx & 63;
        cs[f * 32 + i] = control[(size_t)b * 32768 + i * 1024 + f0 + f];
    }
    __syncthreads();

#pragma unroll
    for (int p = 0; p < 8; p++) {
        int f = w * 8 + p;
        float c = cs[f * 32 + lane];
        float gd = 0.f, gdd = 0.f, gbb = 0.f;
#pragma unroll
        for (int k = 0; k < 32; k++) {
            float ck = cs[f * 32 + k];
            gd  += Gs[lane * 33 + k] * ck;
            gdd += GDs[lane * 33 + k] * ck;
            gbb += GBs[lane * 33 + k] * ck;
        }
        float nv2 = c * c, nx2 = c * gd;
        warp_sum2(nv2, nx2);
        float tsd = c * gdd, tsb = c * gbb;
        warp_sum2(tsd, tsb);

        float nv = sqrt_pos(nv2), nx = sqrt_pos(nx2);
        float facp = __fdividef(fminf(nx, nv), nx + EPS);
        float nproj = facp * nx;
        float nxd = facp * sqrt_pos(tsd);
        float nxb = facp * sqrt_pos(tsb);
        float fd = facp * __fdividef(fminf(nxd, nproj), nxd + EPS);
        float fb = facp * __fdividef(fminf(nxb, nproj), nxb + EPS);

        int r = (f0 + f) * 32 + b;
        g_cd[(size_t)r * 32 + lane] = fd * c;
        g_cb[(size_t)r * 32 + lane] = fb * c;
        if (lane == 0) g_nb2[r] = fb * fb * tsb;
    }
}

// ---------------- k_olay: out = windowed OLA of the yd term (rank-32 on the fly) ----
__global__ __launch_bounds__(512) void k_olay(float* __restrict__ out) {
    __shared__ __align__(16) float cds[65 * 32];

    int bx = blockIdx.x;
    int b = bx & 31, f0 = (bx >> 5) * 64;
    int tid = threadIdx.x;

    u64 w1p[16], w0p[16];
    const u64* r1p = (const u64*)&g_WDwt[(size_t)tid * 32];
    const u64* r0p = (const u64*)&g_WDwt[(size_t)(tid + 512) * 32];
#pragma unroll
    for (int m = 0; m < 16; m++) { w1p[m] = r1p[m]; w0p[m] = r0p[m]; }

    for (int idx = tid; idx < 65 * 8; idx += 512) {
        int k = idx >> 3, quad = idx & 7;
        int f = f0 - 1 + k;
        float4 v = make_float4(0.f, 0.f, 0.f, 0.f);
        if (f >= 0) v = *(const float4*)&g_cd[((size_t)(f * 32 + b)) * 32 + quad * 4];
        *(float4*)&cds[k * 32 + quad * 4] = v;
    }
    __syncthreads();

    size_t obase = (size_t)b * 524288 + (size_t)f0 * 512 + tid;
#pragma unroll 4
    for (int k = 0; k < 64; k++) {
        const u64* c1 = (const u64*)&cds[(k + 1) * 32];
        const u64* c0 = (const u64*)&cds[k * 32];
        u64 a0 = 0, a1 = 0;
#pragma unroll
        for (int m = 0; m < 16; m++) {
            fma2(a0, w1p[m], c1[m]);
            fma2(a1, w0p[m], c0[m]);
        }
        float2 u0 = upk2(a0), u1 = upk2(a1);
        out[obase + (size_t)k * 512] = (u0.x + u0.y) + (u1.x + u1.y);
    }
}

// ---------------- k_yb: g_yb = cb[32768,32] @ WB[32,128] ----------------
__global__ __launch_bounds__(256) void k_yb() {
    __shared__ __align__(16) float ats[64 * 32];
    __shared__ __align__(16) float bts[32 * 128];
    int r0 = blockIdx.x * 64;
    int tid = threadIdx.x;

    const float4* A4 = (const float4*)(g_cb + (size_t)r0 * 32);
    ((float4*)ats)[tid] = A4[tid];
    ((float4*)ats)[tid + 256] = A4[tid + 256];
#pragma unroll
    for (int p = 0; p < 4; p++) {
        int idx = tid + p * 256;
        int i = idx >> 5, q = idx & 31;
        *(float4*)&bts[i * 128 + q * 4] = *(const float4*)&g_WB[i * 128 + q * 4];
    }
    __syncthreads();

    int tm = tid >> 4, tn = tid & 15;
    u64 acc[4][4];
#pragma unroll
    for (int i = 0; i < 4; i++)
#pragma unroll
        for (int p = 0; p < 4; p++) acc[i][p] = 0;

#pragma unroll
    for (int k = 0; k < 32; k++) {
        const u64* br = (const u64*)&bts[k * 128 + tn * 8];
        u64 b0 = br[0], b1 = br[1], b2 = br[2], b3 = br[3];
#pragma unroll
        for (int p = 0; p < 4; p++) {
            float av = ats[(tm * 4 + p) * 32 + k];
            u64 a2 = pk2(av, av);
            fma2(acc[p][0], a2, b0);
            fma2(acc[p][1], a2, b1);
            fma2(acc[p][2], a2, b2);
            fma2(acc[p][3], a2, b3);
        }
    }
#pragma unroll
    for (int p = 0; p < 4; p++) {
        int row = r0 + tm * 4 + p;
        float2 c0 = upk2(acc[p][0]), c1 = upk2(acc[p][1]);
        float2 c2 = upk2(acc[p][2]), c3 = upk2(acc[p][3]);
        float4* dst = (float4*)&g_yb[(size_t)row * 128 + tn * 8];
        dst[0] = make_float4(c0.x, c0.y, c1.x, c1.y);
        dst[1] = make_float4(c2.x, c2.y, c3.x, c3.y);
    }
}

// ---------------- k_pow: Mp[k] = Mp[k/2] @ Mp[k-k/2] ----------------
__global__ __launch_bounds__(256) void k_pow(int kstart) {
    int k = kstart + blockIdx.y;
    int a = k >> 1, b2 = k - a;
    const float* A  = g_Mp + (size_t)a  * 16384;
    const float* Bp = g_Mp + (size_t)b2 * 16384;
    float* O = g_Mp + (size_t)k * 16384;

    __shared__ float Ash[16][128];
    int r0 = blockIdx.x * 16;
    int tid = threadIdx.x;
#pragma unroll
    for (int q = 0; q < 8; q++) {
        int idx = q * 256 + tid;
        Ash[idx >> 7][idx & 127] = A[r0 * 128 + idx];
    }
    __syncthreads();

    int rl = tid >> 4;
    int c0 = (tid & 15) * 8;
    u64 acc[4] = {0, 0, 0, 0};
    for (int m = 0; m < 128; m++) {
        float av = Ash[rl][m];
        u64 a2 = pk2(av, av);
        const u64* brow = (const u64*)(Bp + m * 128 + c0);
        fma2(acc[0], a2, brow[0]);
        fma2(acc[1], a2, brow[1]);
        fma2(acc[2], a2, brow[2]);
        fma2(acc[3], a2, brow[3]);
    }
    float* orow = O + (r0 + rl) * 128 + c0;
#pragma unroll
    for (int p = 0; p < 4; p++) {
        float2 f = upk2(acc[p]);
        orow[2 * p] = f.x; orow[2 * p + 1] = f.y;
    }
}

// ---------------- k_wbmp: WBMp[i] = WB @ Mp[15-i] ----------------
__global__ __launch_bounds__(256) void k_wbmp() {
    int i = blockIdx.x;
    const float* Mw = g_Mp + (size_t)(15 - i) * 16384;
    __shared__ float wbs[32 * 132];
    int tid = threadIdx.x;
#pragma unroll
    for (int p = 0; p < 16; p++) {
        int idx = tid + p * 256;
        int row = idx >> 7, k = idx & 127;
        wbs[row * 132 + k] = g_WB[row * 128 + k];
    }
    __syncthreads();

    int row = tid >> 3, j0 = (tid & 7) * 16;
    u64 acc[8] = {0, 0, 0, 0, 0, 0, 0, 0};
    for (int k = 0; k < 128; k++) {
        float wv = wbs[row * 132 + k];
        u64 w2 = pk2(wv, wv);
        const u64* mr = (const u64*)(Mw + k * 128 + j0);
#pragma unroll
        for (int p = 0; p < 8; p++) fma2(acc[p], w2, mr[p]);
    }
    float* o = g_WBMp + ((size_t)i * 32 + row) * 128 + j0;
#pragma unroll
    for (int p = 0; p < 8; p++) {
        float2 f = upk2(acc[p]);
        o[2 * p] = f.x; o[2 * p + 1] = f.y;
    }
}

// ---------------- k_rcg: rc[c*32+b] = sum_i cb[(c*16+i)*32+b] @ WBMp[i] ----------------
__global__ __launch_bounds__(256) void k_rcg() {
    __shared__ __align__(16) float ats[64 * 32];
    __shared__ __align__(16) float bts[32 * 128];
    int r0 = blockIdx.x * 64;
    int tid = threadIdx.x;
    int tm = tid >> 4, tn = tid & 15;

    u64 acc[4][4];
#pragma unroll
    for (int ii = 0; ii < 4; ii++)
#pragma unroll
        for (int p = 0; p < 4; p++) acc[ii][p] = 0;

    for (int i = 0; i < W_; i++) {
        __syncthreads();
#pragma unroll
        for (int p = 0; p < 2; p++) {
            int idx = tid + p * 256;
            int m = idx >> 3, quad = idx & 7;
            int cb = r0 + m, c = cb >> 5, b = cb & 31;
            size_t fr = (size_t)((c * W_ + i) * 32 + b);
            ((float4*)ats)[idx] = *(const float4*)&g_cb[fr * 32 + quad * 4];
        }
#pragma unroll
        for (int p = 0; p < 4; p++) {
            int idx = tid + p * 256;
            int ii = idx >> 5, q = idx & 31;
            *(float4*)&bts[ii * 128 + q * 4] =
                *(const float4*)&g_WBMp[((size_t)i * 32 + ii) * 128 + q * 4];
        }
        __syncthreads();
#pragma unroll
        for (int k = 0; k < 32; k++) {
            const u64* br = (const u64*)&bts[k * 128 + tn * 8];
            u64 b0 = br[0], b1 = br[1], b2 = br[2], b3 = br[3];
#pragma unroll
            for (int p = 0; p < 4; p++) {
                float av = ats[(tm * 4 + p) * 32 + k];
                u64 a2 = pk2(av, av);
                fma2(acc[p][0], a2, b0);
                fma2(acc[p][1], a2, b1);
                fma2(acc[p][2], a2, b2);
                fma2(acc[p][3], a2, b3);
            }
        }
    }
#pragma unroll
    for (int p = 0; p < 4; p++) {
        int row = r0 + tm * 4 + p;
        float2 c0 = upk2(acc[p][0]), c1 = upk2(acc[p][1]);
        float2 c2 = upk2(acc[p][2]), c3 = upk2(acc[p][3]);
        float4* dst = (float4*)&g_rc[(size_t)row * 128 + tn * 8];
        dst[0] = make_float4(c0.x, c0.y, c1.x, c1.y);
        dst[1] = make_float4(c2.x, c2.y, c3.x, c3.y);
    }
}

// ---------------- k_chain: S_{c+1} = S_c @ Mp[16] + r_c ----------------
__global__ __launch_bounds__(128) void k_chain() {
    int b = blockIdx.x;
    int j = threadIdx.x;
    __shared__ __align__(16) float ssh[2][128];

    u64 mcol[64];
    const float* M16 = g_Mp + (size_t)16 * 16384;
#pragma unroll
    for (int m = 0; m < 64; m++)
        mcol[m] = pk2(M16[(2 * m) * 128 + j], M16[(2 * m + 1) * 128 + j]);

    ssh[0][j] = 0.f;
    g_S[(0 * 32 + b) * 128 + j] = 0.f;
    __syncthreads();

    for (int c = 0; c < NC_ - 1; c++) {
        int cur = c & 1;
        const u64* sv = (const u64*)ssh[cur];
        u64 a0 = 0, a1 = 0, a2 = 0, a3 = 0;
#pragma unroll
        for (int m = 0; m < 64; m += 4) {
            fma2(a0, mcol[m + 0], sv[m + 0]);
            fma2(a1, mcol[m + 1], sv[m + 1]);
            fma2(a2, mcol[m + 2], sv[m + 2]);
            fma2(a3, mcol[m + 3], sv[m + 3]);
        }
        float2 u0 = upk2(a0), u1 = upk2(a1), u2 = upk2(a2), u3 = upk2(a3);
        float y = ((u0.x + u0.y) + (u1.x + u1.y)) + ((u2.x + u2.y) + (u3.x + u3.y));
        float sn = y + g_rc[((size_t)(c * 32 + b)) * 128 + j];
        ssh[cur ^ 1][j] = sn;
        g_S[((c + 1) * 32 + b) * 128 + j] = sn;
        __syncthreads();
    }
}

// ---------------- k_expand: within-chunk linear steps -> x_t ----------------
__global__ __launch_bounds__(128) void k_expand() {
    int c = blockIdx.x >> 5;
    int b = blockIdx.x & 31;
    int j = threadIdx.x;
    __shared__ __align__(16) float ssh[2][128];

    u64 mcol[64];
    const float* M1 = g_Mp + (size_t)16384;
#pragma unroll
    for (int m = 0; m < 64; m++)
        mcol[m] = pk2(M1[(2 * m) * 128 + j], M1[(2 * m + 1) * 128 + j]);

    ssh[0][j] = g_S[((size_t)(c * 32 + b)) * 128 + j];
    __syncthreads();

    for (int i = 0; i < W_; i++) {
        int t = c * W_ + i;
        int cur = i & 1;
        const u64* sv = (const u64*)ssh[cur];
        u64 a0 = 0, a1 = 0, a2 = 0, a3 = 0;
#pragma unroll
        for (int m = 0; m < 64; m += 4) {
            fma2(a0, mcol[m + 0], sv[m + 0]);
            fma2(a1, mcol[m + 1], sv[m + 1]);
            fma2(a2, mcol[m + 2], sv[m + 2]);
            fma2(a3, mcol[m + 3], sv[m + 3]);
        }
        float2 u0 = upk2(a0), u1 = upk2(a1), u2 = upk2(a2), u3 = upk2(a3);
        float y = ((u0.x + u0.y) + (u1.x + u1.y)) + ((u2.x + u2.y) + (u3.x + u3.y));
        size_t row = (size_t)(t * 32 + b) * 128;
        g_x[row + j] = y;
        float sn = y + g_yb[row + j];
        ssh[cur ^ 1][j] = sn;
        __syncthreads();
    }
}

// ---------------- k_fac: exact factors from speculative x; writes sp, nsp, bad ----------------
__global__ __launch_bounds__(256) void k_fac() {
    int tid = threadIdx.x;
    int warp = tid >> 5, lane = tid & 31;
    int r = blockIdx.x * 8 + warp;
    int t = r >> 5;

    float4 x4 = ((const float4*)(g_x + (size_t)r * 128))[lane];

    float4 s4 = make_float4(0.f, 0.f, 0.f, 0.f);
    if (t > 0) {
        int pr = r - 32;
        float4 xp = ((const float4*)(g_x + (size_t)pr * 128))[lane];
        float4 bp = ((const float4*)(g_yb + (size_t)pr * 128))[lane];
        s4 = make_float4(xp.x + bp.x, xp.y + bp.y, xp.z + bp.z, xp.w + bp.w);
    }

    float px = x4.x * x4.x + x4.y * x4.y + x4.z * x4.z + x4.w * x4.w;
    float ps = s4.x * s4.x + s4.y * s4.y + s4.z * s4.z + s4.w * s4.w;
    warp_sum2(px, ps);
    float nxs = sqrt_pos(px), ns = sqrt_pos(ps);
    float fac = __fdividef(fminf(nxs, ns), nxs + EPS);

    float4 sp4 = make_float4(fac * x4.x, fac * x4.y, fac * x4.z, fac * x4.w);
    ((float4*)(g_sp + (size_t)r * 128))[lane] = sp4;
    if (lane == 0) {
        g_nsp[r] = fac * nxs;
        if (px > ps) g_bad = 1;
    }
}

// ---------------- k_repair: exact sequential scan, runs only if g_bad ----------------
__global__ __launch_bounds__(512) void k_repair(const float* __restrict__ A) {
    if (g_bad == 0) return;

    __shared__ __align__(16) float s_sh[S_];
    __shared__ float part[512];
    __shared__ float red1[4], red2[4];

    int b = blockIdx.x;
    int tid = threadIdx.x;
    int q = tid >> 7, j = tid & 127;
    int warp = tid >> 5, lane = tid & 31;

    u64 apk[16];
#pragma unroll
    for (int m = 0; m < 16; m++)
        apk[m] = pk2(A[(q * 32 + 2 * m) * 128 + j], A[(q * 32 + 2 * m + 1) * 128 + j]);

    if (tid < 128) s_sh[tid] = 0.f;
    float ns = 0.f;
    float binp_cur = 0.f, binp_nxt = 0.f;
    float nb2_cur = 0.f, nb2_nxt = 0.f;
    if (tid < 128) {
        binp_cur = g_yb[(size_t)b * 128 + j];
        nb2_cur = g_nb2[b];
    }
    __syncthreads();

    for (int t = 0; t < F_; t++) {
        if (tid < 128 && t + 1 < F_) {
            size_t rn = (size_t)((t + 1) * 32 + b);
            binp_nxt = g_yb[rn * 128 + j];
            nb2_nxt = g_nb2[rn];
        }
        u64 a0 = 0, a1 = 0, a2 = 0, a3 = 0;
#pragma unroll
        for (int m = 0; m < 16; m += 4) {
            fma2(a0, apk[m + 0], *(const u64*)&s_sh[q * 32 + 2 * m + 0]);
            fma2(a1, apk[m + 1], *(const u64*)&s_sh[q * 32 + 2 * m + 2]);
            fma2(a2, apk[m + 2], *(const u64*)&s_sh[q * 32 + 2 * m + 4]);
            fma2(a3, apk[m + 3], *(const u64*)&s_sh[q * 32 + 2 * m + 6]);
        }
        float2 u0 = upk2(a0), u1 = upk2(a1), u2 = upk2(a2), u3 = upk2(a3);
        part[tid] = ((u0.x + u0.y) + (u1.x + u1.y)) + ((u2.x + u2.y) + (u3.x + u3.y));
        __syncthreads();

        float xs = 0.f;
        if (tid < 128) {
            xs = (part[j] + part[128 + j]) + (part[256 + j] + part[384 + j]);
            float px = xs * xs, pxb = xs * binp_cur;
            warp_sum2(px, pxb);
            if (lane == 0) { red1[warp] = px; red2[warp] = pxb; }
        }
        __syncthreads();

        if (tid < 128) {
            float nxs2 = (red1[0] + red1[1]) + (red1[2] + red1[3]);
            float xb   = (red2[0] + red2[1]) + (red2[2] + red2[3]);
            float nxs = sqrt_pos(nxs2);
            float fac = __fdividef(fminf(nxs, ns), nxs + EPS);
            float sp = fac * xs;
            g_sp[(size_t)(t * 32 + b) * 128 + j] = sp;
            if (tid == 0) g_nsp[t * 32 + b] = fac * nxs;
            s_sh[j] = sp + binp_cur;
            ns = sqrt_pos(fac * fac * nxs2 + 2.f * fac * xb + nb2_cur);
            binp_cur = binp_nxt;
            nb2_cur = nb2_nxt;
        }
        __syncthreads();
    }
}

// ---------------- k_ygo: Y(=g_x) = sp[32768,128] @ G_O[128,128]  (tiled GEMM) ----------------
__global__ __launch_bounds__(256) void k_ygo() {
    __shared__ __align__(16) float As[32][64];
    __shared__ __align__(16) float Bs[32][128];
    int r0 = blockIdx.x * 64;
    int tid = threadIdx.x;
    int tm = tid >> 4, tn = tid & 15;

    u64 acc[4][4];
#pragma unroll
    for (int i = 0; i < 4; i++)
#pragma unroll
        for (int p = 0; p < 4; p++) acc[i][p] = 0;

    const float4* A4 = (const float4*)g_sp;
    const float4* B4 = (const float4*)g_GO;

    for (int kc = 0; kc < 128; kc += 32) {
        __syncthreads();
#pragma unroll
        for (int ii = 0; ii < 2; ii++) {
            int slot = tid + ii * 256;             // 0..511 -> 64 rows x 8 k-float4
            int m = slot >> 3, k4 = slot & 7;
            float4 v = A4[(size_t)(r0 + m) * 32 + (kc >> 2) + k4];
            As[k4 * 4 + 0][m] = v.x;
            As[k4 * 4 + 1][m] = v.y;
            As[k4 * 4 + 2][m] = v.z;
            As[k4 * 4 + 3][m] = v.w;
        }
#pragma unroll
        for (int ii = 0; ii < 4; ii++) {
            int slot = tid + ii * 256;             // 0..1023 -> 32 k x 32 n-float4
            int k = slot >> 5, n4 = slot & 31;
            float4 v = B4[(size_t)(kc + k) * 32 + n4];
            *((float4*)&Bs[k][n4 * 4]) = v;
        }
        __syncthreads();
#pragma unroll
        for (int k = 0; k < 32; k++) {
            const u64* br = (const u64*)&Bs[k][tn * 8];
            u64 b0 = br[0], b1 = br[1], b2 = br[2], b3 = br[3];
#pragma unroll
            for (int p = 0; p < 4; p++) {
                float av = As[k][tm * 4 + p];
                u64 a2 = pk2(av, av);
                fma2(acc[p][0], a2, b0);
                fma2(acc[p][1], a2, b1);
                fma2(acc[p][2], a2, b2);
                fma2(acc[p][3], a2, b3);
            }
        }
    }
#pragma unroll
    for (int p = 0; p < 4; p++) {
        int row = r0 + tm * 4 + p;
        float2 c0 = upk2(acc[p][0]), c1 = upk2(acc[p][1]);
        float2 c2 = upk2(acc[p][2]), c3 = upk2(acc[p][3]);
        float4* dst = (float4*)&g_x[(size_t)row * 128 + tn * 8];
        dst[0] = make_float4(c0.x, c0.y, c1.x, c1.y);
        dst[1] = make_float4(c2.x, c2.y, c3.x, c3.y);
    }
}

// ---------------- k_fcd: fc[r] from ||xc||^2 = sp_r . Y_r ----------------
__global__ __launch_bounds__(256) void k_fcd() {
    int tid = threadIdx.x;
    int warp = tid >> 5, lane = tid & 31;
    int r = blockIdx.x * 8 + warp;

    float4 sp4 = ((const float4*)(g_sp + (size_t)r * 128))[lane];
    float4 y4  = ((const float4*)(g_x  + (size_t)r * 128))[lane];
    float q = sp4.x * y4.x + sp4.y * y4.y + sp4.z * y4.z + sp4.w * y4.w;
    float nxc2 = warp_sum(q);
    float nxc = sqrt_pos(nxc2);
    if (lane == 0)
        g_fc[r] = __fdividef(fminf(nxc, g_nsp[r]), nxc + EPS);
}

// ---------------- k_gemm2: out += (fc1*sp[r1] || fc0*sp[r0]) @ Omw  (K=256, fused OLA) ----------------
#define KC 32
__global__ __launch_bounds__(256) void k_gemm2(float* __restrict__ out) {
    __shared__ float As[KC][128];
    __shared__ float Bs[KC][128];
    __shared__ float fc1s[128], fc0s[128];

    int m0 = blockIdx.y * 128, n0 = blockIdx.x * 128;
    int tid = threadIdx.x;
    int tm = tid >> 4, tn = tid & 15;

    if (tid < 128) {
        fc1s[tid] = g_fc[m0 + tid];
        fc0s[tid] = (m0 + tid >= 32) ? g_fc[m0 + tid - 32] : 0.f;
    }

    u64 acc2[8][4];
#pragma unroll
    for (int i = 0; i < 8; i++)
#pragma unroll
        for (int p = 0; p < 4; p++) acc2[i][p] = 0;

    const float4* A4 = (const float4*)g_sp;
    const float4* B4 = (const float4*)g_Omw;

    for (int kc = 0; kc < 256; kc += KC) {
        __syncthreads();
#pragma unroll
        for (int ii = 0; ii < 4; ii++) {
            int slot = tid + ii * 256;
            int m = slot >> 3, k4 = slot & 7;
            float4 v;
            float sc;
            if (kc < 128) {
                v = A4[(size_t)(m0 + m) * 32 + (kc >> 2) + k4];
                sc = fc1s[m];
            } else {
                int r2 = m0 + m - 32;
                if (r2 >= 0) {
                    v = A4[(size_t)r2 * 32 + ((kc - 128) >> 2) + k4];
                    sc = fc0s[m];
                } else {
                    v = make_float4(0.f, 0.f, 0.f, 0.f);
                    sc = 0.f;
                }
            }
            As[k4 * 4 + 0][m] = v.x * sc;
            As[k4 * 4 + 1][m] = v.y * sc;
            As[k4 * 4 + 2][m] = v.z * sc;
            As[k4 * 4 + 3][m] = v.w * sc;
        }
#pragma unroll
        for (int ii = 0; ii < 4; ii++) {
            int slot = tid + ii * 256;
            int k = slot >> 5, n4 = slot & 31;
            float4 v = B4[(size_t)(kc + k) * 128 + (n0 >> 2) + n4];
            *((float4*)&Bs[k][n4 * 4]) = v;
        }
        __syncthreads();
#pragma unroll
        for (int k = 0; k < KC; k++) {
            float4 af0 = *(const float4*)&As[k][tm * 8];
            float4 af1 = *(const float4*)&As[k][tm * 8 + 4];
            u64 bp0 = *(const u64*)&Bs[k][tn * 8 + 0];
            u64 bp1 = *(const u64*)&Bs[k][tn * 8 + 2];
            u64 bp2 = *(const u64*)&Bs[k][tn * 8 + 4];
            u64 bp3 = *(const u64*)&Bs[k][tn * 8 + 6];
            u64 ad[8];
            ad[0] = pk2(af0.x, af0.x); ad[1] = pk2(af0.y, af0.y);
            ad[2] = pk2(af0.z, af0.z); ad[3] = pk2(af0.w, af0.w);
            ad[4] = pk2(af1.x, af1.x); ad[5] = pk2(af1.y, af1.y);
            ad[6] = pk2(af1.z, af1.z); ad[7] = pk2(af1.w, af1.w);
#pragma unroll
            for (int mi = 0; mi < 8; mi++) {
                fma2(acc2[mi][0], ad[mi], bp0);
                fma2(acc2[mi][1], ad[mi], bp1);
                fma2(acc2[mi][2], ad[mi], bp2);
                fma2(acc2[mi][3], ad[mi], bp3);
            }
        }
    }

#pragma unroll
    for (int mi = 0; mi < 8; mi++) {
        int row = m0 + tm * 8 + mi;
        int b = row & 31, f = row >> 5;
        float2 c0 = upk2(acc2[mi][0]), c1 = upk2(acc2[mi][1]);
        float2 c2 = upk2(acc2[mi][2]), c3 = upk2(acc2[mi][3]);
        float4* dst = (float4*)(out + (size_t)b * 524288 + (size_t)f * 512 + n0 + tn * 8);
        float4 d0 = dst[0], d1 = dst[1];
        dst[0] = make_float4(d0.x + c0.x, d0.y + c0.y, d0.z + c1.x, d0.w + c1.y);
        dst[1] = make_float4(d1.x + c2.x, d1.y + c2.y, d1.z + c3.x, d1.w + c3.y);
    }
}

extern "C" void kernel_launch(void* const* d_in, const int* in_sizes, int n_in,
                              void* d_out, int out_size) {
    const float* control  = (const float*)d_in[0];
    const float* proj_w   = (const float*)d_in[1];
    const float* state_m  = (const float*)d_in[2];
    const float* input_m  = (const float*)d_in[3];
    const float* output_m = (const float*)d_in[4];
    const float* direct_m = (const float*)d_in[5];
    float* out = (float*)d_out;

    k_prep<<<161, 256>>>(proj_w, direct_m, input_m, state_m);  // #1
    k_gram2w<<<4, 256>>>();                                    // #2
    k_factors<<<512, 256>>>(control);                          // #3
    k_olay<<<512, 512>>>(out);                                 // #4  <- profiled
    k_go<<<64, 256>>>(output_m);                               // #5
    k_omw<<<512, 256>>>(output_m);                             // #6
    k_pow<<<dim3(8, 1), 256>>>(2);                             // #7
    k_pow<<<dim3(8, 2), 256>>>(3);                             // #8
    k_pow<<<dim3(8, 4), 256>>>(5);                             // #9
    k_pow<<<dim3(8, 8), 256>>>(9);                             // #10
    k_wbmp<<<16, 256>>>();                                     // #11
    k_yb<<<512, 256>>>();                                      // #12
    k_rcg<<<32, 256>>>();                                      // #13
    k_chain<<<32, 128>>>();                                    // #14
    k_expand<<<NC_ * 32, 128>>>();                             // #15
    k_fac<<<4096, 256>>>();                                    // #16
    k_repair<<<32, 512>>>(state_m);                            // #17
    k_ygo<<<512, 256>>>();                                     // #18
    k_fcd<<<4096, 256>>>();                                    // #19
    k_gemm2<<<dim3(4, 256), 256>>>(out);                       // #20
}

// round 16
// speedup vs baseline: 1.1919x; 1.1490x over previous
#include <cuda_runtime.h>
#include <math.h>

#define EPS 1e-8f
#define B_   32
#define CPD_ 32
#define F_   1024
#define D_   1024
#define S_   128
#define BF_  (B_*F_)        // 32768
#define W_   16             // chunk width
#define NC_  64             // number of chunks

typedef unsigned long long u64;

// ---------------- device scratch ----------------
__device__ float g_WD[CPD_*D_];        // W @ direct   [32][1024]
__device__ float g_WB[CPD_*S_];        // W @ input    [32][128]
__device__ float g_G[CPD_*CPD_];       // W W^T
__device__ float g_GD[CPD_*CPD_];      // WD WD^T
__device__ float g_GB[CPD_*CPD_];      // WB WB^T
__device__ float g_WDwt[D_*CPD_];      // window-folded WD transpose [j][i]
__device__ float g_cd[(size_t)BF_*CPD_]; // fd-scaled control rows [r][32]
__device__ float g_cb[(size_t)BF_*CPD_]; // fb-scaled control rows [r][32]
__device__ float g_yb[(size_t)BF_*S_]; // b rows [f*32+b][128]
__device__ float g_nb2[BF_];           // ||b||^2 per frame
__device__ float g_Mp[17*S_*S_];       // M^0..M^16
__device__ float g_WBMp[W_*CPD_*S_];   // WB @ M^(15-i), i=0..15
__device__ float g_rc[NC_*B_*S_];      // chunk residuals
__device__ float g_S[NC_*B_*S_];       // chunk-start states
__device__ float g_x[(size_t)BF_*S_];  // speculative x_t = s_t M
__device__ float g_sp[(size_t)BF_*S_]; // s'_t rows
__device__ float g_nsp[BF_];           // ||s'_t||
__device__ float g_xc[(size_t)BF_*D_]; // unscaled c GEMM out
__device__ float g_cs2[BF_];           // row sumsq of g_xc (atomic)
__device__ float g_fc[BF_];            // c factor
__device__ int   g_bad;                // clamp-active flag

// ---------------- f32x2 helpers ----------------
__device__ __forceinline__ void fma2(u64 &acc, u64 a, u64 b) {
    asm("fma.rn.f32x2 %0, %1, %2, %0;" : "+l"(acc) : "l"(a), "l"(b));
}
__device__ __forceinline__ u64 pk2(float lo, float hi) {
    u64 r; asm("mov.b64 %0, {%1, %2};" : "=l"(r) : "f"(lo), "f"(hi)); return r;
}
__device__ __forceinline__ float2 upk2(u64 v) {
    float lo, hi; asm("mov.b64 {%0, %1}, %2;" : "=f"(lo), "=f"(hi) : "l"(v));
    return make_float2(lo, hi);
}
__device__ __forceinline__ float warp_sum(float v) {
#pragma unroll
    for (int m = 16; m > 0; m >>= 1) v += __shfl_xor_sync(0xffffffffu, v, m);
    return v;
}
__device__ __forceinline__ void warp_sum2(float &a, float &b) {
#pragma unroll
    for (int m = 16; m > 0; m >>= 1) {
        a += __shfl_xor_sync(0xffffffffu, a, m);
        b += __shfl_xor_sync(0xffffffffu, b, m);
    }
}
__device__ __forceinline__ float sqrt_pos(float x) {
    return x * rsqrtf(fmaxf(x, 1e-30f));
}

// ---------------- prep: WD, WB, Gram G, zero cs2, Mp[0]=I, Mp[1]=M ----------------
__global__ __launch_bounds__(256) void k_prep(const float* __restrict__ W,
                                              const float* __restrict__ Dm,
                                              const float* __restrict__ In,
                                              const float* __restrict__ M) {
    int bx = blockIdx.x, tid = threadIdx.x;
    if (bx < 128) {                       // WD
        int gid = bx * 256 + tid;
        int i = gid >> 10, j = gid & 1023;
        const float* wr = W + i * 1024;
        float a0 = 0.f, a1 = 0.f, a2 = 0.f, a3 = 0.f;
#pragma unroll 4
        for (int k = 0; k < 1024; k += 4) {
            a0 += wr[k + 0] * Dm[(k + 0) * D_ + j];
            a1 += wr[k + 1] * Dm[(k + 1) * D_ + j];
            a2 += wr[k + 2] * Dm[(k + 2) * D_ + j];
            a3 += wr[k + 3] * Dm[(k + 3) * D_ + j];
        }
        g_WD[gid] = (a0 + a1) + (a2 + a3);
    } else if (bx < 144) {                // WB
        int gid = (bx - 128) * 256 + tid;
        int i = gid >> 7, j = gid & 127;
        const float* wr = W + i * 1024;
        float a0 = 0.f, a1 = 0.f, a2 = 0.f, a3 = 0.f;
#pragma unroll 4
        for (int k = 0; k < 1024; k += 4) {
            a0 += wr[k + 0] * In[(k + 0) * S_ + j];
            a1 += wr[k + 1] * In[(k + 1) * S_ + j];
            a2 += wr[k + 2] * In[(k + 2) * S_ + j];
            a3 += wr[k + 3] * In[(k + 3) * S_ + j];
        }
        g_WB[gid] = (a0 + a1) + (a2 + a3);
    } else if (bx == 144) {               // Gram of W
        __shared__ float Wt[64 * 33];
        float acc[4] = {0.f, 0.f, 0.f, 0.f};
        for (int k0 = 0; k0 < 1024; k0 += 64) {
            __syncthreads();
            for (int lin = tid; lin < 2048; lin += 256) {
                int i = lin >> 6, kk = lin & 63;
                Wt[kk * 33 + i] = W[i * 1024 + k0 + kk];
            }
            __syncthreads();
#pragma unroll
            for (int q = 0; q < 4; q++) {
                int o = tid * 4 + q;
                int i = o >> 5, i2 = o & 31;
                float a = 0.f;
#pragma unroll 8
                for (int kk = 0; kk < 64; kk++) a += Wt[kk * 33 + i] * Wt[kk * 33 + i2];
                acc[q] += a;
            }
        }
#pragma unroll
        for (int q = 0; q < 4; q++) g_G[tid * 4 + q] = acc[q];
    } else if (bx < 161) {                // zero g_cs2
        int base = (bx - 145) * 2048;
#pragma unroll
        for (int ii = 0; ii < 8; ii++) g_cs2[base + ii * 256 + tid] = 0.f;
    } else if (bx < 169) {                // Mp[1] = M
        int base = (bx - 161) * 2048;
#pragma unroll
        for (int ii = 0; ii < 8; ii++) {
            int idx = base + ii * 256 + tid;
            g_Mp[16384 + idx] = M[idx];
        }
    } else {                              // Mp[0] = I, zero g_bad
        int base = (bx - 169) * 2048;
#pragma unroll
        for (int ii = 0; ii < 8; ii++) {
            int idx = base + ii * 256 + tid;
            g_Mp[idx] = ((idx >> 7) == (idx & 127)) ? 1.f : 0.f;
        }
        if (bx == 169 && tid == 0) g_bad = 0;
    }
}

// ---------------- gram2w: GD (bx0), GB (bx1), window-folded WD transpose (bx2,3) ----------------
__global__ __launch_bounds__(256) void k_gram2w() {
    int bx = blockIdx.x, tid = threadIdx.x;
    if (bx < 2) {
        const float* src = bx ? g_WB : g_WD;
        float* dst       = bx ? g_GB : g_GD;
        int K            = bx ? 128 : 1024;
        __shared__ float Wt[64 * 33];
        float acc[4] = {0.f, 0.f, 0.f, 0.f};
        for (int k0 = 0; k0 < K; k0 += 64) {
            __syncthreads();
            for (int lin = tid; lin < 2048; lin += 256) {
                int i = lin >> 6, kk = lin & 63;
                Wt[kk * 33 + i] = src[i * K + k0 + kk];
            }
            __syncthreads();
#pragma unroll
            for (int q = 0; q < 4; q++) {
                int o = tid * 4 + q;
                int i = o >> 5, i2 = o & 31;
                float a = 0.f;
#pragma unroll 8
                for (int kk = 0; kk < 64; kk++) a += Wt[kk * 33 + i] * Wt[kk * 33 + i2];
                acc[q] += a;
            }
        }
#pragma unroll
        for (int q = 0; q < 4; q++) dst[tid * 4 + q] = acc[q];
    } else {
        int j0 = (bx - 2) * 512;
        for (int idx = tid; idx < 16384; idx += 256) {
            int i2 = idx >> 9;
            int j = j0 + (idx & 511);
            float w = 0.5f * (1.0f - __cosf((float)j * 6.13592315154256491e-3f));
            g_WDwt[(size_t)j * 32 + i2] = g_WD[i2 * 1024 + j] * w;
        }
    }
}

// ---------------- factors: per-row fd, fb via 32x32 quadforms; writes cd, cb, nb2 ----------------
__global__ __launch_bounds__(256) void k_factors(const float* __restrict__ control) {
    __shared__ float cs[64 * 32];
    __shared__ float Gs[32 * 33], GDs[32 * 33], GBs[32 * 33];

    int bx = blockIdx.x;
    int b = bx & 31, f0 = (bx >> 5) * 64;
    int tid = threadIdx.x;
    int w = tid >> 5, lane = tid & 31;

    for (int lin = tid; lin < 1024; lin += 256) {
        int i = lin >> 5, k = lin & 31;
        Gs[i * 33 + k]  = g_G[lin];
        GDs[i * 33 + k] = g_GD[lin];
        GBs[i * 33 + k] = g_GB[lin];
    }
#pragma unroll
    for (int p = 0; p < 8; p++) {
        int idx = tid + p * 256;
        int i = idx >> 6, f = idx & 63;
        cs[f * 32 + i] = control[(size_t)b * 32768 + i * 1024 + f0 + f];
    }
    __syncthreads();

#pragma unroll
    for (int p = 0; p < 8; p++) {
        int f = w * 8 + p;
        float c = cs[f * 32 + lane];
        float gd = 0.f, gdd = 0.f, gbb = 0.f;
#pragma unroll
        for (int k = 0; k < 32; k++) {
            float ck = cs[f * 32 + k];
            gd  += Gs[lane * 33 + k] * ck;
            gdd += GDs[lane * 33 + k] * ck;
            gbb += GBs[lane * 33 + k] * ck;
        }
        float nv2 = c * c, nx2 = c * gd;
        warp_sum2(nv2, nx2);
        float tsd = c * gdd, tsb = c * gbb;
        warp_sum2(tsd, tsb);

        float nv = sqrt_pos(nv2), nx = sqrt_pos(nx2);
        float facp = __fdividef(fminf(nx, nv), nx + EPS);
        float nproj = facp * nx;
        float nxd = facp * sqrt_pos(tsd);
        float nxb = facp * sqrt_pos(tsb);
        float fd = facp * __fdividef(fminf(nxd, nproj), nxd + EPS);
        float fb = facp * __fdividef(fminf(nxb, nproj), nxb + EPS);

        int r = (f0 + f) * 32 + b;
        g_cd[(size_t)r * 32 + lane] = fd * c;
        g_cb[(size_t)r * 32 + lane] = fb * c;
        if (lane == 0) g_nb2[r] = fb * fb * tsb;
    }
}

// ---------------- k_olay: out = windowed OLA of the yd term (rank-32 on the fly) ----
__global__ __launch_bounds__(512) void k_olay(float* __restrict__ out) {
    __shared__ __align__(16) float cds[65 * 32];

    int bx = blockIdx.x;
    int b = bx & 31, f0 = (bx >> 5) * 64;
    int tid = threadIdx.x;

    u64 w1p[16], w0p[16];
    const u64* r1p = (const u64*)&g_WDwt[(size_t)tid * 32];
    const u64* r0p = (const u64*)&g_WDwt[(size_t)(tid + 512) * 32];
#pragma unroll
    for (int m = 0; m < 16; m++) { w1p[m] = r1p[m]; w0p[m] = r0p[m]; }

    for (int idx = tid; idx < 65 * 8; idx += 512) {
        int k = idx >> 3, quad = idx & 7;
        int f = f0 - 1 + k;
        float4 v = make_float4(0.f, 0.f, 0.f, 0.f);
        if (f >= 0) v = *(const float4*)&g_cd[((size_t)(f * 32 + b)) * 32 + quad * 4];
        *(float4*)&cds[k * 32 + quad * 4] = v;
    }
    __syncthreads();

    size_t obase = (size_t)b * 524288 + (size_t)f0 * 512 + tid;
#pragma unroll 4
    for (int k = 0; k < 64; k++) {
        const u64* c1 = (const u64*)&cds[(k + 1) * 32];
        const u64* c0 = (const u64*)&cds[k * 32];
        u64 a0 = 0, a1 = 0;
#pragma unroll
        for (int m = 0; m < 16; m++) {
            fma2(a0, w1p[m], c1[m]);
            fma2(a1, w0p[m], c0[m]);
        }
        float2 u0 = upk2(a0), u1 = upk2(a1);
        out[obase + (size_t)k * 512] = (u0.x + u0.y) + (u1.x + u1.y);
    }
}

// ---------------- k_yb: g_yb = cb[32768,32] @ WB[32,128] ----------------
__global__ __launch_bounds__(256) void k_yb() {
    __shared__ __align__(16) float ats[64 * 32];
    __shared__ __align__(16) float bts[32 * 128];
    int r0 = blockIdx.x * 64;
    int tid = threadIdx.x;

    const float4* A4 = (const float4*)(g_cb + (size_t)r0 * 32);
    ((float4*)ats)[tid] = A4[tid];
    ((float4*)ats)[tid + 256] = A4[tid + 256];
#pragma unroll
    for (int p = 0; p < 4; p++) {
        int idx = tid + p * 256;
        int i = idx >> 5, q = idx & 31;
        *(float4*)&bts[i * 128 + q * 4] = *(const float4*)&g_WB[i * 128 + q * 4];
    }
    __syncthreads();

    int tm = tid >> 4, tn = tid & 15;
    u64 acc[4][4];
#pragma unroll
    for (int i = 0; i < 4; i++)
#pragma unroll
        for (int p = 0; p < 4; p++) acc[i][p] = 0;

#pragma unroll
    for (int k = 0; k < 32; k++) {
        const u64* br = (const u64*)&bts[k * 128 + tn * 8];
        u64 b0 = br[0], b1 = br[1], b2 = br[2], b3 = br[3];
#pragma unroll
        for (int p = 0; p < 4; p++) {
            float av = ats[(tm * 4 + p) * 32 + k];
            u64 a2 = pk2(av, av);
            fma2(acc[p][0], a2, b0);
            fma2(acc[p][1], a2, b1);
            fma2(acc[p][2], a2, b2);
            fma2(acc[p][3], a2, b3);
        }
    }
#pragma unroll
    for (int p = 0; p < 4; p++) {
        int row = r0 + tm * 4 + p;
        float2 c0 = upk2(acc[p][0]), c1 = upk2(acc[p][1]);
        float2 c2 = upk2(acc[p][2]), c3 = upk2(acc[p][3]);
        float4* dst = (float4*)&g_yb[(size_t)row * 128 + tn * 8];
        dst[0] = make_float4(c0.x, c0.y, c1.x, c1.y);
        dst[1] = make_float4(c2.x, c2.y, c3.x, c3.y);
    }
}

// ---------------- k_pow: Mp[k] = Mp[k/2] @ Mp[k-k/2] ----------------
__global__ __launch_bounds__(256) void k_pow(int kstart) {
    int k = kstart + blockIdx.y;
    int a = k >> 1, b2 = k - a;
    const float* A  = g_Mp + (size_t)a  * 16384;
    const float* Bp = g_Mp + (size_t)b2 * 16384;
    float* O = g_Mp + (size_t)k * 16384;

    __shared__ float Ash[16][128];
    int r0 = blockIdx.x * 16;
    int tid = threadIdx.x;
#pragma unroll
    for (int q = 0; q < 8; q++) {
        int idx = q * 256 + tid;
        Ash[idx >> 7][idx & 127] = A[r0 * 128 + idx];
    }
    __syncthreads();

    int rl = tid >> 4;
    int c0 = (tid & 15) * 8;
    u64 acc[4] = {0, 0, 0, 0};
    for (int m = 0; m < 128; m++) {
        float av = Ash[rl][m];
        u64 a2 = pk2(av, av);
        const u64* brow = (const u64*)(Bp + m * 128 + c0);
        fma2(acc[0], a2, brow[0]);
        fma2(acc[1], a2, brow[1]);
        fma2(acc[2], a2, brow[2]);
        fma2(acc[3], a2, brow[3]);
    }
    float* orow = O + (r0 + rl) * 128 + c0;
#pragma unroll
    for (int p = 0; p < 4; p++) {
        float2 f = upk2(acc[p]);
        orow[2 * p] = f.x; orow[2 * p + 1] = f.y;
    }
}

// ---------------- k_wbmp: WBMp[i] = WB @ Mp[15-i] ----------------
__global__ __launch_bounds__(256) void k_wbmp() {
    int i = blockIdx.x;
    const float* Mw = g_Mp + (size_t)(15 - i) * 16384;
    __shared__ float wbs[32 * 132];
    int tid = threadIdx.x;
#pragma unroll
    for (int p = 0; p < 16; p++) {
        int idx = tid + p * 256;
        int row = idx >> 7, k = idx & 127;
        wbs[row * 132 + k] = g_WB[row * 128 + k];
    }
    __syncthreads();

    int row = tid >> 3, j0 = (tid & 7) * 16;
    u64 acc[8] = {0, 0, 0, 0, 0, 0, 0, 0};
    for (int k = 0; k < 128; k++) {
        float wv = wbs[row * 132 + k];
        u64 w2 = pk2(wv, wv);
        const u64* mr = (const u64*)(Mw + k * 128 + j0);
#pragma unroll
        for (int p = 0; p < 8; p++) fma2(acc[p], w2, mr[p]);
    }
    float* o = g_WBMp + ((size_t)i * 32 + row) * 128 + j0;
#pragma unroll
    for (int p = 0; p < 8; p++) {
        float2 f = upk2(acc[p]);
        o[2 * p] = f.x; o[2 * p + 1] = f.y;
    }
}

// ---------------- k_rcg: rc[c*32+b] = sum_i cb[(c*16+i)*32+b] @ WBMp[i] ----------------
__global__ __launch_bounds__(256) void k_rcg() {
    __shared__ __align__(16) float ats[64 * 32];
    __shared__ __align__(16) float bts[32 * 128];
    int r0 = blockIdx.x * 64;
    int tid = threadIdx.x;
    int tm = tid >> 4, tn = tid & 15;

    u64 acc[4][4];
#pragma unroll
    for (int ii = 0; ii < 4; ii++)
#pragma unroll
        for (int p = 0; p < 4; p++) acc[ii][p] = 0;

    for (int i = 0; i < W_; i++) {
        __syncthreads();
#pragma unroll
        for (int p = 0; p < 2; p++) {
            int idx = tid + p * 256;
            int m = idx >> 3, quad = idx & 7;
            int cb = r0 + m, c = cb >> 5, b = cb & 31;
            size_t fr = (size_t)((c * W_ + i) * 32 + b);
            ((float4*)ats)[idx] = *(const float4*)&g_cb[fr * 32 + quad * 4];
        }
#pragma unroll
        for (int p = 0; p < 4; p++) {
            int idx = tid + p * 256;
            int ii = idx >> 5, q = idx & 31;
            *(float4*)&bts[ii * 128 + q * 4] =
                *(const float4*)&g_WBMp[((size_t)i * 32 + ii) * 128 + q * 4];
        }
        __syncthreads();
#pragma unroll
        for (int k = 0; k < 32; k++) {
            const u64* br = (const u64*)&bts[k * 128 + tn * 8];
            u64 b0 = br[0], b1 = br[1], b2 = br[2], b3 = br[3];
#pragma unroll
            for (int p = 0; p < 4; p++) {
                float av = ats[(tm * 4 + p) * 32 + k];
                u64 a2 = pk2(av, av);
                fma2(acc[p][0], a2, b0);
                fma2(acc[p][1], a2, b1);
                fma2(acc[p][2], a2, b2);
                fma2(acc[p][3], a2, b3);
            }
        }
    }
#pragma unroll
    for (int p = 0; p < 4; p++) {
        int row = r0 + tm * 4 + p;
        float2 c0 = upk2(acc[p][0]), c1 = upk2(acc[p][1]);
        float2 c2 = upk2(acc[p][2]), c3 = upk2(acc[p][3]);
        float4* dst = (float4*)&g_rc[(size_t)row * 128 + tn * 8];
        dst[0] = make_float4(c0.x, c0.y, c1.x, c1.y);
        dst[1] = make_float4(c2.x, c2.y, c3.x, c3.y);
    }
}

// ---------------- k_chain: S_{c+1} = S_c @ Mp[16] + r_c ----------------
__global__ __launch_bounds__(128) void k_chain() {
    int b = blockIdx.x;
    int j = threadIdx.x;
    __shared__ __align__(16) float ssh[2][128];

    u64 mcol[64];
    const float* M16 = g_Mp + (size_t)16 * 16384;
#pragma unroll
    for (int m = 0; m < 64; m++)
        mcol[m] = pk2(M16[(2 * m) * 128 + j], M16[(2 * m + 1) * 128 + j]);

    ssh[0][j] = 0.f;
    g_S[(0 * 32 + b) * 128 + j] = 0.f;
    __syncthreads();

    for (int c = 0; c < NC_ - 1; c++) {
        int cur = c & 1;
        const u64* sv = (const u64*)ssh[cur];
        u64 a0 = 0, a1 = 0, a2 = 0, a3 = 0;
#pragma unroll
        for (int m = 0; m < 64; m += 4) {
            fma2(a0, mcol[m + 0], sv[m + 0]);
            fma2(a1, mcol[m + 1], sv[m + 1]);
            fma2(a2, mcol[m + 2], sv[m + 2]);
            fma2(a3, mcol[m + 3], sv[m + 3]);
        }
        float2 u0 = upk2(a0), u1 = upk2(a1), u2 = upk2(a2), u3 = upk2(a3);
        float y = ((u0.x + u0.y) + (u1.x + u1.y)) + ((u2.x + u2.y) + (u3.x + u3.y));
        float sn = y + g_rc[((size_t)(c * 32 + b)) * 128 + j];
        ssh[cur ^ 1][j] = sn;
        g_S[((c + 1) * 32 + b) * 128 + j] = sn;
        __syncthreads();
    }
}

// ---------------- k_expand: within-chunk linear steps -> x_t ----------------
__global__ __launch_bounds__(128) void k_expand() {
    int c = blockIdx.x >> 5;
    int b = blockIdx.x & 31;
    int j = threadIdx.x;
    __shared__ __align__(16) float ssh[2][128];

    u64 mcol[64];
    const float* M1 = g_Mp + (size_t)16384;
#pragma unroll
    for (int m = 0; m < 64; m++)
        mcol[m] = pk2(M1[(2 * m) * 128 + j], M1[(2 * m + 1) * 128 + j]);

    ssh[0][j] = g_S[((size_t)(c * 32 + b)) * 128 + j];
    __syncthreads();

    for (int i = 0; i < W_; i++) {
        int t = c * W_ + i;
        int cur = i & 1;
        const u64* sv = (const u64*)ssh[cur];
        u64 a0 = 0, a1 = 0, a2 = 0, a3 = 0;
#pragma unroll
        for (int m = 0; m < 64; m += 4) {
            fma2(a0, mcol[m + 0], sv[m + 0]);
            fma2(a1, mcol[m + 1], sv[m + 1]);
            fma2(a2, mcol[m + 2], sv[m + 2]);
            fma2(a3, mcol[m + 3], sv[m + 3]);
        }
        float2 u0 = upk2(a0), u1 = upk2(a1), u2 = upk2(a2), u3 = upk2(a3);
        float y = ((u0.x + u0.y) + (u1.x + u1.y)) + ((u2.x + u2.y) + (u3.x + u3.y));
        size_t row = (size_t)(t * 32 + b) * 128;
        g_x[row + j] = y;
        float sn = y + g_yb[row + j];
        ssh[cur ^ 1][j] = sn;
        __syncthreads();
    }
}

// ---------------- k_fac: exact factors from speculative x ----------------
__global__ __launch_bounds__(256) void k_fac() {
    int tid = threadIdx.x;
    int warp = tid >> 5, lane = tid & 31;
    int r = blockIdx.x * 8 + warp;
    int t = r >> 5;

    float4 x4 = ((const float4*)(g_x + (size_t)r * 128))[lane];

    float4 s4 = make_float4(0.f, 0.f, 0.f, 0.f);
    if (t > 0) {
        int pr = r - 32;
        float4 xp = ((const float4*)(g_x + (size_t)pr * 128))[lane];
        float4 bp = ((const float4*)(g_yb + (size_t)pr * 128))[lane];
        s4 = make_float4(xp.x + bp.x, xp.y + bp.y, xp.z + bp.z, xp.w + bp.w);
    }

    float px = x4.x * x4.x + x4.y * x4.y + x4.z * x4.z + x4.w * x4.w;
    float ps = s4.x * s4.x + s4.y * s4.y + s4.z * s4.z + s4.w * s4.w;
    warp_sum2(px, ps);
    float nxs = sqrt_pos(px), ns = sqrt_pos(ps);
    float fac = __fdividef(fminf(nxs, ns), nxs + EPS);

    float4 sp4 = make_float4(fac * x4.x, fac * x4.y, fac * x4.z, fac * x4.w);
    ((float4*)(g_sp + (size_t)r * 128))[lane] = sp4;
    if (lane == 0) {
        g_nsp[r] = fac * nxs;
        if (px > ps) g_bad = 1;
    }
}

// ---------------- k_repair: exact sequential scan, runs only if g_bad ----------------
__global__ __launch_bounds__(512) void k_repair(const float* __restrict__ A) {
    if (g_bad == 0) return;

    __shared__ __align__(16) float s_sh[S_];
    __shared__ float part[512];
    __shared__ float red1[4], red2[4];

    int b = blockIdx.x;
    int tid = threadIdx.x;
    int q = tid >> 7, j = tid & 127;
    int warp = tid >> 5, lane = tid & 31;

    u64 apk[16];
#pragma unroll
    for (int m = 0; m < 16; m++)
        apk[m] = pk2(A[(q * 32 + 2 * m) * 128 + j], A[(q * 32 + 2 * m + 1) * 128 + j]);

    if (tid < 128) s_sh[tid] = 0.f;
    float ns = 0.f;
    float binp_cur = 0.f, binp_nxt = 0.f;
    float nb2_cur = 0.f, nb2_nxt = 0.f;
    if (tid < 128) {
        binp_cur = g_yb[(size_t)b * 128 + j];
        nb2_cur = g_nb2[b];
    }
    __syncthreads();

    for (int t = 0; t < F_; t++) {
        if (tid < 128 && t + 1 < F_) {
            size_t rn = (size_t)((t + 1) * 32 + b);
            binp_nxt = g_yb[rn * 128 + j];
            nb2_nxt = g_nb2[rn];
        }
        u64 a0 = 0, a1 = 0, a2 = 0, a3 = 0;
#pragma unroll
        for (int m = 0; m < 16; m += 4) {
            fma2(a0, apk[m + 0], *(const u64*)&s_sh[q * 32 + 2 * m + 0]);
            fma2(a1, apk[m + 1], *(const u64*)&s_sh[q * 32 + 2 * m + 2]);
            fma2(a2, apk[m + 2], *(const u64*)&s_sh[q * 32 + 2 * m + 4]);
            fma2(a3, apk[m + 3], *(const u64*)&s_sh[q * 32 + 2 * m + 6]);
        }
        float2 u0 = upk2(a0), u1 = upk2(a1), u2 = upk2(a2), u3 = upk2(a3);
        part[tid] = ((u0.x + u0.y) + (u1.x + u1.y)) + ((u2.x + u2.y) + (u3.x + u3.y));
        __syncthreads();

        float xs = 0.f;
        if (tid < 128) {
            xs = (part[j] + part[128 + j]) + (part[256 + j] + part[384 + j]);
            float px = xs * xs, pxb = xs * binp_cur;
            warp_sum2(px, pxb);
            if (lane == 0) { red1[warp] = px; red2[warp] = pxb; }
        }
        __syncthreads();

        if (tid < 128) {
            float nxs2 = (red1[0] + red1[1]) + (red1[2] + red1[3]);
            float xb   = (red2[0] + red2[1]) + (red2[2] + red2[3]);
            float nxs = sqrt_pos(nxs2);
            float fac = __fdividef(fminf(nxs, ns), nxs + EPS);
            float sp = fac * xs;
            g_sp[(size_t)(t * 32 + b) * 128 + j] = sp;
            if (tid == 0) g_nsp[t * 32 + b] = fac * nxs;
            s_sh[j] = sp + binp_cur;
            ns = sqrt_pos(fac * fac * nxs2 + 2.f * fac * xb + nb2_cur);
            binp_cur = binp_nxt;
            nb2_cur = nb2_nxt;
        }
        __syncthreads();
    }
}

// ---------------- XC = Sprime[32768,128] @ output[128,1024] ----------------
#define KC 32
__global__ __launch_bounds__(256) void k_gemm(const float* __restrict__ Bm) {
    __shared__ float As[KC][128];
    __shared__ float Bs[KC][128];
    __shared__ float rowred[128];

    int m0 = blockIdx.y * 128, n0 = blockIdx.x * 128;
    int tid = threadIdx.x;
    int tm = tid >> 4, tn = tid & 15;

    u64 acc2[8][4];
#pragma unroll
    for (int i = 0; i < 8; i++)
#pragma unroll
        for (int p = 0; p < 4; p++) acc2[i][p] = 0;
    if (tid < 128) rowred[tid] = 0.f;

    const float4* A4 = (const float4*)g_sp;
    const float4* B4 = (const float4*)Bm;

    for (int kc = 0; kc < 128; kc += KC) {
        __syncthreads();
#pragma unroll
        for (int ii = 0; ii < 4; ii++) {
            int slot = tid + ii * 256;
            int m = slot >> 3, k4 = slot & 7;
            float4 v = A4[(size_t)(m0 + m) * 32 + (kc >> 2) + k4];
            As[k4 * 4 + 0][m] = v.x;
            As[k4 * 4 + 1][m] = v.y;
            As[k4 * 4 + 2][m] = v.z;
            As[k4 * 4 + 3][m] = v.w;
        }
#pragma unroll
        for (int ii = 0; ii < 4; ii++) {
            int slot = tid + ii * 256;
            int k = slot >> 5, n4 = slot & 31;
            float4 v = B4[(size_t)(kc + k) * 256 + (n0 >> 2) + n4];
            *((float4*)&Bs[k][n4 * 4]) = v;
        }
        __syncthreads();
#pragma unroll
        for (int k = 0; k < KC; k++) {
            float4 af0 = *(const float4*)&As[k][tm * 8];
            float4 af1 = *(const float4*)&As[k][tm * 8 + 4];
            u64 bp0 = *(const u64*)&Bs[k][tn * 8 + 0];
            u64 bp1 = *(const u64*)&Bs[k][tn * 8 + 2];
            u64 bp2 = *(const u64*)&Bs[k][tn * 8 + 4];
            u64 bp3 = *(const u64*)&Bs[k][tn * 8 + 6];
            u64 ad[8];
            ad[0] = pk2(af0.x, af0.x); ad[1] = pk2(af0.y, af0.y);
            ad[2] = pk2(af0.z, af0.z); ad[3] = pk2(af0.w, af0.w);
            ad[4] = pk2(af1.x, af1.x); ad[5] = pk2(af1.y, af1.y);
            ad[6] = pk2(af1.z, af1.z); ad[7] = pk2(af1.w, af1.w);
#pragma unroll
            for (int mi = 0; mi < 8; mi++) {
                fma2(acc2[mi][0], ad[mi], bp0);
                fma2(acc2[mi][1], ad[mi], bp1);
                fma2(acc2[mi][2], ad[mi], bp2);
                fma2(acc2[mi][3], ad[mi], bp3);
            }
        }
    }

#pragma unroll
    for (int mi = 0; mi < 8; mi++) {
        int row = m0 + tm * 8 + mi;
        float2 c0 = upk2(acc2[mi][0]), c1 = upk2(acc2[mi][1]);
        float2 c2 = upk2(acc2[mi][2]), c3 = upk2(acc2[mi][3]);
        float rs = c0.x * c0.x + c0.y * c0.y + c1.x * c1.x + c1.y * c1.y
                 + c2.x * c2.x + c2.y * c2.y + c3.x * c3.x + c3.y * c3.y;
        float4* dst = (float4*)&g_xc[(size_t)row * 1024 + n0 + tn * 8];
        dst[0] = make_float4(c0.x, c0.y, c1.x, c1.y);
        dst[1] = make_float4(c2.x, c2.y, c3.x, c3.y);
        atomicAdd(&rowred[tm * 8 + mi], rs);
    }
    __syncthreads();
    if (tid < 128) atomicAdd(&g_cs2[m0 + tid], rowred[tid]);
}

// ---------------- c factors ----------------
__global__ void k_fc() {
    int r = blockIdx.x * 256 + threadIdx.x;
    if (r >= BF_) return;
    float nxc = sqrt_pos(g_cs2[r]);
    g_fc[r] = __fdividef(fminf(nxc, g_nsp[r]), nxc + EPS);
}

// ---------------- k_olax: out += fc * window * xc (vectorized: 4 outputs/thread) ----------------
__global__ __launch_bounds__(256) void k_olax(float* __restrict__ out) {
    size_t idx4 = ((size_t)blockIdx.x * 256 + threadIdx.x) * 4;
    int b = (int)(idx4 >> 19);
    int i = (int)(idx4 & 524287);
    int f1 = i >> 9, j1 = i & 511;        // j1 multiple of 4
    int r1 = (f1 << 5) + b;

    float fc1 = g_fc[r1];
    float4 x1 = *(const float4*)&g_xc[(size_t)r1 * 1024 + j1];
    float4 o = *(float4*)&out[idx4];

    float c0 = __cosf((float)(j1 + 0) * 6.13592315154256491e-3f);
    float c1 = __cosf((float)(j1 + 1) * 6.13592315154256491e-3f);
    float c2 = __cosf((float)(j1 + 2) * 6.13592315154256491e-3f);
    float c3 = __cosf((float)(j1 + 3) * 6.13592315154256491e-3f);

    o.x += fc1 * (0.5f * (1.0f - c0)) * x1.x;
    o.y += fc1 * (0.5f * (1.0f - c1)) * x1.y;
    o.z += fc1 * (0.5f * (1.0f - c2)) * x1.z;
    o.w += fc1 * (0.5f * (1.0f - c3)) * x1.w;

    if (f1 > 0) {
        int r0 = r1 - 32;
        float fc0 = g_fc[r0];
        float4 x0 = *(const float4*)&g_xc[(size_t)r0 * 1024 + j1 + 512];
        o.x += fc0 * (0.5f * (1.0f + c0)) * x0.x;
        o.y += fc0 * (0.5f * (1.0f + c1)) * x0.y;
        o.z += fc0 * (0.5f * (1.0f + c2)) * x0.z;
        o.w += fc0 * (0.5f * (1.0f + c3)) * x0.w;
    }
    *(float4*)&out[idx4] = o;
}

extern "C" void kernel_launch(void* const* d_in, const int* in_sizes, int n_in,
                              void* d_out, int out_size) {
    const float* control  = (const float*)d_in[0];
    const float* proj_w   = (const float*)d_in[1];
    const float* state_m  = (const float*)d_in[2];
    const float* input_m  = (const float*)d_in[3];
    const float* output_m = (const float*)d_in[4];
    const float* direct_m = (const float*)d_in[5];
    float* out = (float*)d_out;

    k_prep<<<177, 256>>>(proj_w, direct_m, input_m, state_m);  // #1
    k_gram2w<<<4, 256>>>();                                    // #2
    k_factors<<<512, 256>>>(control);                          // #3
    k_olay<<<512, 512>>>(out);                                 // #4  <- profiled (control)
    k_pow<<<dim3(8, 1), 256>>>(2);                             // #5
    k_pow<<<dim3(8, 2), 256>>>(3);                             // #6
    k_pow<<<dim3(8, 4), 256>>>(5);                             // #7
    k_pow<<<dim3(8, 8), 256>>>(9);                             // #8
    k_wbmp<<<16, 256>>>();                                     // #9
    k_yb<<<512, 256>>>();                                      // #10
    k_rcg<<<32, 256>>>();                                      // #11
    k_chain<<<32, 128>>>();                                    // #12
    k_expand<<<NC_ * 32, 128>>>();                             // #13
    k_fac<<<4096, 256>>>();                                    // #14
    k_repair<<<32, 512>>>(state_m);                            // #15
    k_gemm<<<dim3(8, 256), 256>>>(output_m);                   // #16
    k_fc<<<128, 256>>>();                                      // #17
    k_olax<<<16384, 256>>>(out);                               // #18
}